// round 12
// baseline (speedup 1.0000x reference)
#include <cuda_runtime.h>
#include <cuda_bf16.h>
#include <cstdint>

// ============================================================================
// 4-layer pyramidal BiGRU. B=32, H=512, 3H=1536.
// Layers l=0..3: T = 1024,512,256,128 ; din = 240,2048,2048,2048
// ============================================================================

#define REC_THREADS 256

// ---------------- static device scratch ----------------
__device__ float g_xzf[50331648];                 // [32][1024][1536] max
__device__ float g_xzb[50331648];
__device__ unsigned int g_flag[2 * 512];          // [dir][64 ctas] stride-8
__device__ unsigned char g_mask[65536];           // per-layer offsets
__device__ __nv_bfloat16 g_whi[19611648], g_wlo[19611648];
__device__ __nv_bfloat16 g_inhi[7864320],  g_inlo[7864320];
__device__ __nv_bfloat16 g_yh0[33554432],  g_yl0[33554432];
__device__ __nv_bfloat16 g_yh1[16777216],  g_yl1[16777216];
__device__ __nv_bfloat16 g_hhi[4 * 16384], g_hlo[4 * 16384];

// ---------------- mma / ldmatrix ----------------
#define MMA_BF16(c, a, b0, b1)                                              \
    asm volatile("mma.sync.aligned.m16n8k16.row.col.f32.bf16.bf16.f32 "     \
        "{%0,%1,%2,%3}, {%4,%5,%6,%7}, {%8,%9}, {%0,%1,%2,%3};"             \
        : "+f"((c)[0]), "+f"((c)[1]), "+f"((c)[2]), "+f"((c)[3])            \
        : "r"((a)[0]), "r"((a)[1]), "r"((a)[2]), "r"((a)[3]),               \
          "r"(b0), "r"(b1))

#define LDSM4(R, addr)                                                      \
    asm volatile("ldmatrix.sync.aligned.m8n8.x4.shared.b16 "                \
        "{%0,%1,%2,%3}, [%4];"                                              \
        : "=r"((R)[0]), "=r"((R)[1]), "=r"((R)[2]), "=r"((R)[3])            \
        : "r"(addr))

#define LDSM4T(R, addr)                                                     \
    asm volatile("ldmatrix.sync.aligned.m8n8.x4.trans.shared.b16 "          \
        "{%0,%1,%2,%3}, [%4];"                                              \
        : "=r"((R)[0]), "=r"((R)[1]), "=r"((R)[2]), "=r"((R)[3])            \
        : "r"(addr))

__device__ __forceinline__ unsigned int smaddr(const void* p) {
    return (unsigned int)__cvta_generic_to_shared(p);
}
__device__ __forceinline__ unsigned int bfpack(float a, float b) {
    __nv_bfloat162 h = __floats2bfloat162_rn(a, b);
    return *reinterpret_cast<unsigned int*>(&h);
}

// ============================================================================
// prep kernel: convert 8 weight matrices + layer-0 input to bf16 hi/lo,
// compute layer-0 mask, zero flags.
// ============================================================================
__device__ __forceinline__ void cvt4(float4 v, uint2& hi, uint2& lo) {
    __nv_bfloat162 h0 = __floats2bfloat162_rn(v.x, v.y);
    __nv_bfloat162 h1 = __floats2bfloat162_rn(v.z, v.w);
    float2 f0 = __bfloat1622float2(h0);
    float2 f1 = __bfloat1622float2(h1);
    __nv_bfloat162 l0 = __floats2bfloat162_rn(v.x - f0.x, v.y - f0.y);
    __nv_bfloat162 l1 = __floats2bfloat162_rn(v.z - f1.x, v.w - f1.y);
    hi.x = *(unsigned int*)&h0; hi.y = *(unsigned int*)&h1;
    lo.x = *(unsigned int*)&l0; lo.y = *(unsigned int*)&l1;
}

#define WSZ0 368640
#define WSZ1 3145728

__global__ void prep_kernel(const float* __restrict__ in,
                            const float* w0, const float* w1, const float* w2,
                            const float* w3, const float* w4, const float* w5,
                            const float* w6, const float* w7) {
    const float* ws[8] = {w0, w1, w2, w3, w4, w5, w6, w7};
    const int sz[8]  = {WSZ0, WSZ0, WSZ1, WSZ1, WSZ1, WSZ1, WSZ1, WSZ1};
    const int off[8] = {0, WSZ0, 2 * WSZ0, 2 * WSZ0 + WSZ1, 2 * WSZ0 + 2 * WSZ1,
                        2 * WSZ0 + 3 * WSZ1, 2 * WSZ0 + 4 * WSZ1, 2 * WSZ0 + 5 * WSZ1};
    const int gid = blockIdx.x * blockDim.x + threadIdx.x;
    const int stride = gridDim.x * blockDim.x;

    #pragma unroll 1
    for (int w = 0; w < 8; ++w) {
        const float4* W = (const float4*)ws[w];
        uint2* hi = (uint2*)(g_whi + off[w]);
        uint2* lo = (uint2*)(g_wlo + off[w]);
        int n4 = sz[w] >> 2;
        for (int i = gid; i < n4; i += stride) {
            uint2 h, l; cvt4(__ldg(W + i), h, l);
            hi[i] = h; lo[i] = l;
        }
    }
    {
        const float4* X = (const float4*)in;
        uint2* hi = (uint2*)g_inhi; uint2* lo = (uint2*)g_inlo;
        for (int i = gid; i < (7864320 >> 2); i += stride) {
            uint2 h, l; cvt4(__ldg(X + i), h, l);
            hi[i] = h; lo[i] = l;
        }
    }
    for (int r = gid; r < 32768; r += stride) {
        const float4* p = (const float4*)(in + (size_t)r * 240);
        bool any = false;
        for (int i = 0; i < 60; ++i) {
            float4 v = __ldg(p + i);
            any = any | (v.x != 0.f) | (v.y != 0.f) | (v.z != 0.f) | (v.w != 0.f);
            if (any) break;
        }
        g_mask[r] = any ? 1 : 0;
    }
    for (int i = gid; i < 2 * 512; i += stride) g_flag[i] = 0u;
}

// ============================================================================
// Input-projection GEMM: round-10 structure + 2-stage STATIC double buffer.
// bf16 hi/lo, mma.sync, tile 128x128x16, 2 CTAs/SM, masked-tile skip,
// register prefetch, ONE __syncthreads per k-tile (stage rotation).
// SMEM/CTA: 2 x (6144+6144+4352+4352) = 41,984 B (static, 2 CTAs fit).
// ============================================================================
__global__ void __launch_bounds__(256, 2) gemm_xz(
    const __nv_bfloat16* __restrict__ Ahi, const __nv_bfloat16* __restrict__ Alo,
    int lda,
    const __nv_bfloat16* __restrict__ WhiF, const __nv_bfloat16* __restrict__ WloF,
    const __nv_bfloat16* __restrict__ WhiB, const __nv_bfloat16* __restrict__ WloB,
    const float* __restrict__ biasF, const float* __restrict__ biasB,
    float* __restrict__ Cf, float* __restrict__ Cb,
    int K, int Tcur, const unsigned char* __restrict__ mask) {
    __shared__ __align__(16) __nv_bfloat16 a_hi[2][128 * 24], a_lo[2][128 * 24];
    __shared__ __align__(16) __nv_bfloat16 w_hi[2][16 * 136], w_lo[2][16 * 136];

    const int dir = blockIdx.z;
    const int rev = dir;
    const __nv_bfloat16* Whi = dir ? WhiB : WhiF;
    const __nv_bfloat16* Wlo = dir ? WloB : WloF;
    const float* bias = dir ? biasB : biasF;
    float* C = dir ? Cb : Cf;

    const int tid  = threadIdx.x;
    const int lane = tid & 31, wid = tid >> 5;
    const int g = lane >> 2, t4 = lane & 3;
    const int warpM = wid & 3, warpN = wid >> 2;
    const int m0 = blockIdx.y << 7, n0 = blockIdx.x << 7;

    {
        const int b  = m0 / Tcur;
        const int t0 = m0 - b * Tcur;
        const int ttmin = rev ? (Tcur - 128 - t0) : t0;
        if (mask[b * Tcur + ttmin] == 0) return;
    }

    const int ar = tid >> 1;
    const int ak = (tid & 1) << 3;
    const int wk = tid >> 4;
    const int wc = (tid & 15) << 3;

    const __nv_bfloat16 *pAh, *pAl;
    {
        int m  = m0 + ar;
        int bi = m / Tcur;
        int t  = m - bi * Tcur;
        int tt = rev ? (Tcur - 1 - t) : t;
        size_t base = ((size_t)bi * Tcur + tt) * lda + ak;
        pAh = Ahi + base; pAl = Alo + base;
    }
    const __nv_bfloat16* pWh = Whi + (size_t)wk * 1536 + n0 + wc;
    const __nv_bfloat16* pWl = Wlo + (size_t)wk * 1536 + n0 + wc;

    // ldmatrix lane byte-offsets within a stage
    const int aRowL = warpM * 32 + (lane & 15);
    const int aKofL = (lane & 16) >> 1;
    const unsigned int aHi0 = smaddr(a_hi[0]) + (unsigned)((aRowL * 24 + aKofL) * 2);
    const unsigned int aHi1 = smaddr(a_hi[1]) + (unsigned)((aRowL * 24 + aKofL) * 2);
    const unsigned int aLo0 = smaddr(a_lo[0]) + (unsigned)((aRowL * 24 + aKofL) * 2);
    const unsigned int aLo1 = smaddr(a_lo[1]) + (unsigned)((aRowL * 24 + aKofL) * 2);
    const int bCol = warpN * 64 + ((lane & 16) >> 1);
    const unsigned int bHi0 = smaddr(w_hi[0]) + (unsigned)(((lane & 15) * 136 + bCol) * 2);
    const unsigned int bHi1 = smaddr(w_hi[1]) + (unsigned)(((lane & 15) * 136 + bCol) * 2);
    const unsigned int bLo0 = smaddr(w_lo[0]) + (unsigned)(((lane & 15) * 136 + bCol) * 2);
    const unsigned int bLo1 = smaddr(w_lo[1]) + (unsigned)(((lane & 15) * 136 + bCol) * 2);

    float c_[2][8][4];
    #pragma unroll
    for (int mt = 0; mt < 2; ++mt)
        #pragma unroll
        for (int nt = 0; nt < 8; ++nt)
            #pragma unroll
            for (int i = 0; i < 4; ++i) c_[mt][nt][i] = 0.f;

    const int NT = K >> 4;
    uint4 rAh = *(const uint4*)pAh;
    uint4 rAl = *(const uint4*)pAl;
    uint4 rWh = *(const uint4*)pWh;
    uint4 rWl = *(const uint4*)pWl;

    for (int kt = 0; kt < NT; ++kt) {
        const int s = kt & 1;
        *(uint4*)(a_hi[s] + ar * 24 + ak) = rAh;
        *(uint4*)(a_lo[s] + ar * 24 + ak) = rAl;
        *(uint4*)(w_hi[s] + wk * 136 + wc) = rWh;
        *(uint4*)(w_lo[s] + wk * 136 + wc) = rWl;
        __syncthreads();

        if (kt + 1 < NT) {
            int k0 = (kt + 1) << 4;
            rAh = *(const uint4*)(pAh + k0);
            rAl = *(const uint4*)(pAl + k0);
            rWh = *(const uint4*)(pWh + (size_t)k0 * 1536);
            rWl = *(const uint4*)(pWl + (size_t)k0 * 1536);
        }

        const unsigned int aH = s ? aHi1 : aHi0;
        const unsigned int aL = s ? aLo1 : aLo0;
        const unsigned int bH = s ? bHi1 : bHi0;
        const unsigned int bL = s ? bLo1 : bLo0;

        unsigned int afh[2][4], afl[2][4];
        #pragma unroll
        for (int mt = 0; mt < 2; ++mt) {
            LDSM4(afh[mt], aH + mt * 768);
            LDSM4(afl[mt], aL + mt * 768);
        }

        #pragma unroll
        for (int p = 0; p < 4; ++p) {
            unsigned int bh[4], bl[4];
            LDSM4T(bh, bH + p * 32);
            LDSM4T(bl, bL + p * 32);
            #pragma unroll
            for (int s2 = 0; s2 < 2; ++s2) {
                const int nt = 2 * p + s2;
                #pragma unroll
                for (int mt = 0; mt < 2; ++mt) {
                    MMA_BF16(c_[mt][nt], afh[mt], bh[2 * s2], bh[2 * s2 + 1]);
                    MMA_BF16(c_[mt][nt], afh[mt], bl[2 * s2], bl[2 * s2 + 1]);
                    MMA_BF16(c_[mt][nt], afl[mt], bh[2 * s2], bh[2 * s2 + 1]);
                }
            }
        }
        // no trailing sync: next iteration writes the OTHER stage
    }

    #pragma unroll
    for (int nt = 0; nt < 8; ++nt) {
        int col = n0 + warpN * 64 + nt * 8 + t4 * 2;
        float bx = __ldg(bias + col);
        float by = __ldg(bias + col + 1);
        #pragma unroll
        for (int mt = 0; mt < 2; ++mt) {
            int r = m0 + warpM * 32 + mt * 16 + g;
            float2 o0 = {c_[mt][nt][0] + bx, c_[mt][nt][1] + by};
            float2 o1 = {c_[mt][nt][2] + bx, c_[mt][nt][3] + by};
            *(float2*)(C + (size_t)r * 1536 + col)       = o0;
            *(float2*)(C + (size_t)(r + 8) * 1536 + col) = o1;
        }
    }
}

// ============================================================================
// Recurrence on tensor cores — EXACT round-11 version (proven best):
// K-split across 8 warps, register-prefetch staging, partial reduction.
// SMEM: ahi[32][520] | alo[32][520] bf16 | part[8][3][256] f32 | hp[256]
// ============================================================================
#define LDK 520
#define REC_SMEM (2 * 32 * LDK * 2 + 8 * 3 * 256 * 4 + 256 * 4)

__global__ void __launch_bounds__(REC_THREADS, 1) gru_rec_kernel(
    const float* __restrict__ xzf, const float* __restrict__ xzb,
    const float* __restrict__ rkf, const float* __restrict__ rkb,
    const float* __restrict__ bf,  const float* __restrict__ bb,
    const unsigned char* __restrict__ mask,
    float* __restrict__ y32,
    __nv_bfloat16* __restrict__ yhi, __nv_bfloat16* __restrict__ ylo,
    unsigned char* __restrict__ nextmask,
    int T, int flagBase, int writeHidden, float* __restrict__ hiddenOut) {
    extern __shared__ __align__(16) char smraw[];
    __nv_bfloat16* sh_ahi = (__nv_bfloat16*)smraw;                // [32][520]
    __nv_bfloat16* sh_alo = sh_ahi + 32 * LDK;                    // [32][520]
    float* sh_part = (float*)(sh_alo + 32 * LDK);                 // [8][3][256]
    float* sh_hp   = sh_part + 8 * 3 * 256;                       // [256]

    const int tid  = threadIdx.x;
    const int lane = tid & 31, wid = tid >> 5;
    const int dir = blockIdx.x >> 6;
    const int j   = blockIdx.x & 63;
    const int cb  = j << 3;
    const int b   = tid >> 3;
    const int c8  = tid & 7;
    const int col = cb + c8;

    const float* xz = dir ? xzb : xzf;
    const float* rk = dir ? rkb : rkf;
    const float* bi = (dir ? bb : bf) + 1536;   // b[1]

    sh_hp[tid] = 0.f;

    const int t4 = lane & 3;
    const int gcol = lane >> 2;
    unsigned int Bh0[3][4], Bh1[3][4], Bl0[3][4], Bl1[3][4];
    #pragma unroll 1
    for (int gate = 0; gate < 3; ++gate) {
        const float* wcolp = rk + gate * 512 + cb + gcol;
        #pragma unroll
        for (int q = 0; q < 4; ++q) {
            int k0 = (wid * 4 + q) * 16 + t4 * 2;
            float w00 = __ldg(wcolp + (size_t)(k0)     * 1536);
            float w01 = __ldg(wcolp + (size_t)(k0 + 1) * 1536);
            float w10 = __ldg(wcolp + (size_t)(k0 + 8) * 1536);
            float w11 = __ldg(wcolp + (size_t)(k0 + 9) * 1536);
            __nv_bfloat16 h00 = __float2bfloat16(w00), h01 = __float2bfloat16(w01);
            __nv_bfloat16 h10 = __float2bfloat16(w10), h11 = __float2bfloat16(w11);
            Bh0[gate][q] = ((unsigned)*(unsigned short*)&h01 << 16) | *(unsigned short*)&h00;
            Bh1[gate][q] = ((unsigned)*(unsigned short*)&h11 << 16) | *(unsigned short*)&h10;
            Bl0[gate][q] = bfpack(w00 - __bfloat162float(h00), w01 - __bfloat162float(h01));
            Bl1[gate][q] = bfpack(w10 - __bfloat162float(h10), w11 - __bfloat162float(h11));
        }
    }
    const float bz = __ldg(bi + col);
    const float br = __ldg(bi + 512 + col);
    const float bh = __ldg(bi + 1024 + col);
    __syncthreads();

    const unsigned int aB0 = smaddr(sh_ahi) +
        (unsigned)((((lane & 15)) * LDK + ((lane >> 4) << 3)) * 2) + (unsigned)(wid * 128);
    const unsigned int aB1 = aB0 + (unsigned)(16 * LDK * 2);
    const unsigned int loOfs = (unsigned)(32 * LDK * 2);

    unsigned int* myflag = g_flag + dir * 512 + j * 8;
    const unsigned int* pollflag = g_flag + dir * 512 + (tid & 63) * 8;
    const bool maskWriter = (nextmask != nullptr) && (dir == 0) && (j == 0) && (c8 == 0);
    unsigned char mprev = 0;

    for (int t = 0; t < T; ++t) {
        const int tsrc = dir ? (T - 1 - t) : t;
        const size_t xoff = ((size_t)b * T + t) * 1536;
        const float x0 = __ldg(xz + xoff + col);
        const float x1 = __ldg(xz + xoff + 512 + col);
        const float x2 = __ldg(xz + xoff + 1024 + col);
        const unsigned char m = mask[b * T + tsrc];

        if (t > 0) {
            if (tid < 64) {
                unsigned int v;
                unsigned int target = (unsigned int)(flagBase + t);
                do {
                    asm volatile("ld.acquire.gpu.global.u32 %0, [%1];"
                                 : "=r"(v) : "l"(pollflag) : "memory");
                } while (v < target);
            }
            __syncthreads();

            const size_t hsrc = (size_t)(((t & 1) * 2 + dir)) << 14;
            const __nv_bfloat16* ghi = g_hhi + hsrc;
            const __nv_bfloat16* glo = g_hlo + hsrc;
            #pragma unroll
            for (int q = 0; q < 8; ++q) {
                int v = q * 256 + tid;
                int bb2 = v >> 6, kc = v & 63;
                uint4 hv = __ldcg((const uint4*)(ghi + (bb2 << 9) + kc * 8));
                uint4 lv = __ldcg((const uint4*)(glo + (bb2 << 9) + kc * 8));
                *(uint4*)(sh_ahi + bb2 * LDK + kc * 8) = hv;
                *(uint4*)(sh_alo + bb2 * LDK + kc * 8) = lv;
            }
            __syncthreads();

            float acc[3][2][4];
            #pragma unroll
            for (int gg = 0; gg < 3; ++gg)
                #pragma unroll
                for (int mt = 0; mt < 2; ++mt)
                    #pragma unroll
                    for (int i = 0; i < 4; ++i) acc[gg][mt][i] = 0.f;

            #pragma unroll
            for (int q = 0; q < 4; ++q) {
                unsigned int ah[2][4], al[2][4];
                LDSM4(ah[0], aB0 + q * 32);
                LDSM4(ah[1], aB1 + q * 32);
                LDSM4(al[0], aB0 + loOfs + q * 32);
                LDSM4(al[1], aB1 + loOfs + q * 32);
                #pragma unroll
                for (int gg = 0; gg < 3; ++gg) {
                    #pragma unroll
                    for (int mt = 0; mt < 2; ++mt) {
                        MMA_BF16(acc[gg][mt], ah[mt], Bh0[gg][q], Bh1[gg][q]);
                        MMA_BF16(acc[gg][mt], ah[mt], Bl0[gg][q], Bl1[gg][q]);
                        MMA_BF16(acc[gg][mt], al[mt], Bh0[gg][q], Bh1[gg][q]);
                    }
                }
            }
            const int row = lane >> 2, cq = (lane & 3) << 1;
            #pragma unroll
            for (int gg = 0; gg < 3; ++gg) {
                #pragma unroll
                for (int mt = 0; mt < 2; ++mt) {
                    float* gp = sh_part + (wid * 3 + gg) * 256 + (mt * 16 + row) * 8 + cq;
                    gp[0]  = acc[gg][mt][0];
                    gp[1]  = acc[gg][mt][1];
                    gp[64] = acc[gg][mt][2];
                    gp[65] = acc[gg][mt][3];
                }
            }
            __syncthreads();
        }

        float iz = bz, ir = br, ic = bh;
        if (t > 0) {
            #pragma unroll
            for (int w = 0; w < 8; ++w) {
                iz += sh_part[(w * 3 + 0) * 256 + tid];
                ir += sh_part[(w * 3 + 1) * 256 + tid];
                ic += sh_part[(w * 3 + 2) * 256 + tid];
            }
        }

        const float zg = 1.f / (1.f + expf(-(x0 + iz)));
        const float rg = 1.f / (1.f + expf(-(x1 + ir)));
        const float hh = tanhf(x2 + rg * ic);
        const float hp = sh_hp[tid];
        const float hn = zg * hp + (1.f - zg) * hh;
        const float hsel = m ? hn : hp;
        const float yval = m ? hn : 0.f;
        sh_hp[tid] = hsel;

        const size_t hdst = (size_t)((((t + 1) & 1) * 2 + dir)) << 14;
        __nv_bfloat16 h16 = __float2bfloat16(hsel);
        __nv_bfloat16 l16 = __float2bfloat16(hsel - __bfloat162float(h16));
        g_hhi[hdst + (b << 9) + col] = h16;
        g_hlo[hdst + (b << 9) + col] = l16;
        __syncthreads();
        if (tid == 0) {
            unsigned int v = (unsigned int)(flagBase + t + 1);
            asm volatile("st.release.gpu.global.u32 [%0], %1;"
                         :: "l"(myflag), "r"(v) : "memory");
        }

        const size_t yidx = ((size_t)b * T + tsrc) * 1024 + (dir << 9) + col;
        if (yhi) {
            __nv_bfloat16 yh16 = __float2bfloat16(yval);
            yhi[yidx] = yh16;
            ylo[yidx] = __float2bfloat16(yval - __bfloat162float(yh16));
        }
        if (y32) y32[yidx] = yval;
        if (writeHidden && t == T - 1)
            hiddenOut[(b << 10) + (dir << 9) + col] = hsel;
        if (maskWriter) {
            if ((t & 1) == 0) mprev = m;
            else nextmask[b * (T >> 1) + (t >> 1)] = (unsigned char)(mprev | m);
        }
    }
}

// ============================================================================
// Launch sequence (graph-capturable)
// ============================================================================
extern "C" void kernel_launch(void* const* d_in, const int* in_sizes, int n_in,
                              void* d_out, int out_size) {
    (void)in_sizes; (void)n_in; (void)out_size;
    const float* inputs = (const float*)d_in[0];

    const float *k_[4][2], *r_[4][2], *bi_[4][2];
    for (int l = 0; l < 4; ++l)
        for (int d = 0; d < 2; ++d) {
            int base = 3 + l * 6 + d * 3;
            k_[l][d]  = (const float*)d_in[base + 0];
            r_[l][d]  = (const float*)d_in[base + 1];
            bi_[l][d] = (const float*)d_in[base + 2];
        }

    float *xzf, *xzb;
    unsigned char* mk;
    __nv_bfloat16 *whi, *wlo, *inhi, *inlo, *yh0, *yl0, *yh1, *yl1;
    cudaGetSymbolAddress((void**)&xzf, g_xzf);
    cudaGetSymbolAddress((void**)&xzb, g_xzb);
    cudaGetSymbolAddress((void**)&mk, g_mask);
    cudaGetSymbolAddress((void**)&whi, g_whi);
    cudaGetSymbolAddress((void**)&wlo, g_wlo);
    cudaGetSymbolAddress((void**)&inhi, g_inhi);
    cudaGetSymbolAddress((void**)&inlo, g_inlo);
    cudaGetSymbolAddress((void**)&yh0, g_yh0);
    cudaGetSymbolAddress((void**)&yl0, g_yl0);
    cudaGetSymbolAddress((void**)&yh1, g_yh1);
    cudaGetSymbolAddress((void**)&yl1, g_yl1);

    cudaFuncSetAttribute(gru_rec_kernel,
                         cudaFuncAttributeMaxDynamicSharedMemorySize, REC_SMEM);

    float* outp = (float*)d_out;
    float* hid  = outp + (size_t)32 * 128 * 1024;

    prep_kernel<<<2048, 256>>>(inputs, k_[0][0], k_[0][1], k_[1][0], k_[1][1],
                               k_[2][0], k_[2][1], k_[3][0], k_[3][1]);

    const int Ts[4]   = {1024, 512, 256, 128};
    const int Ks[4]   = {240, 2048, 2048, 2048};
    const int ldas[4] = {240, 2048, 2048, 2048};
    const int woff[4][2] = {{0, WSZ0},
                            {2 * WSZ0, 2 * WSZ0 + WSZ1},
                            {2 * WSZ0 + 2 * WSZ1, 2 * WSZ0 + 3 * WSZ1},
                            {2 * WSZ0 + 4 * WSZ1, 2 * WSZ0 + 5 * WSZ1}};
    const int moff[4]  = {0, 32768, 49152, 57344};
    const int fbase[4] = {0, 1024, 1536, 1792};

    const __nv_bfloat16* Ah[4] = {inhi, yh0, yh1, yh0};
    const __nv_bfloat16* Al[4] = {inlo, yl0, yl1, yl0};
    __nv_bfloat16* Yh[4] = {yh0, yh1, yh0, nullptr};
    __nv_bfloat16* Yl[4] = {yl0, yl1, yl0, nullptr};
    float* Y32[4] = {nullptr, nullptr, nullptr, outp};

    for (int l = 0; l < 4; ++l) {
        const int T = Ts[l], K = Ks[l];
        const int rows = 32 * T;

        dim3 grid(12, rows / 128, 2);
        gemm_xz<<<grid, 256>>>(Ah[l], Al[l], ldas[l],
                               whi + woff[l][0], wlo + woff[l][0],
                               whi + woff[l][1], wlo + woff[l][1],
                               bi_[l][0], bi_[l][1],
                               xzf, xzb, K, T, mk + moff[l]);

        gru_rec_kernel<<<128, REC_THREADS, REC_SMEM>>>(
            xzf, xzb, r_[l][0], r_[l][1], bi_[l][0], bi_[l][1],
            mk + moff[l], Y32[l], Yh[l], Yl[l],
            (l < 3) ? (mk + moff[l + 1]) : nullptr,
            T, fbase[l], (l == 3) ? 1 : 0, hid);
    }
}

// round 13
// speedup vs baseline: 1.0698x; 1.0698x over previous
#include <cuda_runtime.h>
#include <cuda_bf16.h>
#include <cstdint>

// ============================================================================
// 4-layer pyramidal BiGRU. B=32, H=512, 3H=1536.
// Layers l=0..3: T = 1024,512,256,128 ; din = 240,2048,2048,2048
// ============================================================================

#define REC_THREADS 256

// ---------------- static device scratch ----------------
__device__ float g_xzf[50331648];                 // [32][1024][1536] max
__device__ float g_xzb[50331648];
__device__ unsigned int g_flag[2 * 512];          // [dir][64 ctas] stride-8
__device__ unsigned char g_mask[65536];           // per-layer offsets
__device__ __nv_bfloat16 g_whi[19611648], g_wlo[19611648];
__device__ __nv_bfloat16 g_inhi[7864320],  g_inlo[7864320];
__device__ __nv_bfloat16 g_yh0[33554432],  g_yl0[33554432];
__device__ __nv_bfloat16 g_yh1[16777216],  g_yl1[16777216];
__device__ __nv_bfloat16 g_hhi[4 * 16384], g_hlo[4 * 16384];

// ---------------- mma / ldmatrix ----------------
#define MMA_BF16(c, a, b0, b1)                                              \
    asm volatile("mma.sync.aligned.m16n8k16.row.col.f32.bf16.bf16.f32 "     \
        "{%0,%1,%2,%3}, {%4,%5,%6,%7}, {%8,%9}, {%0,%1,%2,%3};"             \
        : "+f"((c)[0]), "+f"((c)[1]), "+f"((c)[2]), "+f"((c)[3])            \
        : "r"((a)[0]), "r"((a)[1]), "r"((a)[2]), "r"((a)[3]),               \
          "r"(b0), "r"(b1))

#define LDSM4(R, addr)                                                      \
    asm volatile("ldmatrix.sync.aligned.m8n8.x4.shared.b16 "                \
        "{%0,%1,%2,%3}, [%4];"                                              \
        : "=r"((R)[0]), "=r"((R)[1]), "=r"((R)[2]), "=r"((R)[3])            \
        : "r"(addr))

#define LDSM4T(R, addr)                                                     \
    asm volatile("ldmatrix.sync.aligned.m8n8.x4.trans.shared.b16 "          \
        "{%0,%1,%2,%3}, [%4];"                                              \
        : "=r"((R)[0]), "=r"((R)[1]), "=r"((R)[2]), "=r"((R)[3])            \
        : "r"(addr))

__device__ __forceinline__ unsigned int smaddr(const void* p) {
    return (unsigned int)__cvta_generic_to_shared(p);
}
__device__ __forceinline__ unsigned int bfpack(float a, float b) {
    __nv_bfloat162 h = __floats2bfloat162_rn(a, b);
    return *reinterpret_cast<unsigned int*>(&h);
}

// ============================================================================
// prep kernel: convert 8 weight matrices + layer-0 input to bf16 hi/lo,
// compute layer-0 mask, zero flags.
// ============================================================================
__device__ __forceinline__ void cvt4(float4 v, uint2& hi, uint2& lo) {
    __nv_bfloat162 h0 = __floats2bfloat162_rn(v.x, v.y);
    __nv_bfloat162 h1 = __floats2bfloat162_rn(v.z, v.w);
    float2 f0 = __bfloat1622float2(h0);
    float2 f1 = __bfloat1622float2(h1);
    __nv_bfloat162 l0 = __floats2bfloat162_rn(v.x - f0.x, v.y - f0.y);
    __nv_bfloat162 l1 = __floats2bfloat162_rn(v.z - f1.x, v.w - f1.y);
    hi.x = *(unsigned int*)&h0; hi.y = *(unsigned int*)&h1;
    lo.x = *(unsigned int*)&l0; lo.y = *(unsigned int*)&l1;
}

#define WSZ0 368640
#define WSZ1 3145728

__global__ void prep_kernel(const float* __restrict__ in,
                            const float* w0, const float* w1, const float* w2,
                            const float* w3, const float* w4, const float* w5,
                            const float* w6, const float* w7) {
    const float* ws[8] = {w0, w1, w2, w3, w4, w5, w6, w7};
    const int sz[8]  = {WSZ0, WSZ0, WSZ1, WSZ1, WSZ1, WSZ1, WSZ1, WSZ1};
    const int off[8] = {0, WSZ0, 2 * WSZ0, 2 * WSZ0 + WSZ1, 2 * WSZ0 + 2 * WSZ1,
                        2 * WSZ0 + 3 * WSZ1, 2 * WSZ0 + 4 * WSZ1, 2 * WSZ0 + 5 * WSZ1};
    const int gid = blockIdx.x * blockDim.x + threadIdx.x;
    const int stride = gridDim.x * blockDim.x;

    #pragma unroll 1
    for (int w = 0; w < 8; ++w) {
        const float4* W = (const float4*)ws[w];
        uint2* hi = (uint2*)(g_whi + off[w]);
        uint2* lo = (uint2*)(g_wlo + off[w]);
        int n4 = sz[w] >> 2;
        for (int i = gid; i < n4; i += stride) {
            uint2 h, l; cvt4(__ldg(W + i), h, l);
            hi[i] = h; lo[i] = l;
        }
    }
    {
        const float4* X = (const float4*)in;
        uint2* hi = (uint2*)g_inhi; uint2* lo = (uint2*)g_inlo;
        for (int i = gid; i < (7864320 >> 2); i += stride) {
            uint2 h, l; cvt4(__ldg(X + i), h, l);
            hi[i] = h; lo[i] = l;
        }
    }
    for (int r = gid; r < 32768; r += stride) {
        const float4* p = (const float4*)(in + (size_t)r * 240);
        bool any = false;
        for (int i = 0; i < 60; ++i) {
            float4 v = __ldg(p + i);
            any = any | (v.x != 0.f) | (v.y != 0.f) | (v.z != 0.f) | (v.w != 0.f);
            if (any) break;
        }
        g_mask[r] = any ? 1 : 0;
    }
    for (int i = gid; i < 2 * 512; i += stride) g_flag[i] = 0u;
}

// ============================================================================
// Input-projection GEMM — EXACT round-11 version (proven best):
// bf16 hi/lo, mma.sync, tile 128x128x16, 2 CTAs/SM, masked-tile skip.
// ============================================================================
__global__ void __launch_bounds__(256, 2) gemm_xz(
    const __nv_bfloat16* __restrict__ Ahi, const __nv_bfloat16* __restrict__ Alo,
    int lda,
    const __nv_bfloat16* __restrict__ WhiF, const __nv_bfloat16* __restrict__ WloF,
    const __nv_bfloat16* __restrict__ WhiB, const __nv_bfloat16* __restrict__ WloB,
    const float* __restrict__ biasF, const float* __restrict__ biasB,
    float* __restrict__ Cf, float* __restrict__ Cb,
    int K, int Tcur, const unsigned char* __restrict__ mask) {
    __shared__ __align__(16) __nv_bfloat16 a_hi[128 * 24], a_lo[128 * 24];
    __shared__ __align__(16) __nv_bfloat16 w_hi[16 * 136], w_lo[16 * 136];

    const int dir = blockIdx.z;
    const int rev = dir;
    const __nv_bfloat16* Whi = dir ? WhiB : WhiF;
    const __nv_bfloat16* Wlo = dir ? WloB : WloF;
    const float* bias = dir ? biasB : biasF;
    float* C = dir ? Cb : Cf;

    const int tid  = threadIdx.x;
    const int lane = tid & 31, wid = tid >> 5;
    const int g = lane >> 2, t4 = lane & 3;
    const int warpM = wid & 3, warpN = wid >> 2;
    const int m0 = blockIdx.y << 7, n0 = blockIdx.x << 7;

    {
        const int b  = m0 / Tcur;
        const int t0 = m0 - b * Tcur;
        const int ttmin = rev ? (Tcur - 128 - t0) : t0;
        if (mask[b * Tcur + ttmin] == 0) return;
    }

    const int ar = tid >> 1;
    const int ak = (tid & 1) << 3;
    const int wk = tid >> 4;
    const int wc = (tid & 15) << 3;

    const __nv_bfloat16 *pAh, *pAl;
    {
        int m  = m0 + ar;
        int bi = m / Tcur;
        int t  = m - bi * Tcur;
        int tt = rev ? (Tcur - 1 - t) : t;
        size_t base = ((size_t)bi * Tcur + tt) * lda + ak;
        pAh = Ahi + base; pAl = Alo + base;
    }
    const __nv_bfloat16* pWh = Whi + (size_t)wk * 1536 + n0 + wc;
    const __nv_bfloat16* pWl = Wlo + (size_t)wk * 1536 + n0 + wc;

    const int aRowL = warpM * 32 + (lane & 15);
    const int aKofL = (lane & 16) >> 1;
    const unsigned int aHiAddr = smaddr(a_hi) + (unsigned)((aRowL * 24 + aKofL) * 2);
    const unsigned int aLoAddr = smaddr(a_lo) + (unsigned)((aRowL * 24 + aKofL) * 2);
    const int bCol = warpN * 64 + ((lane & 16) >> 1);
    const unsigned int bHiAddr = smaddr(w_hi) + (unsigned)(((lane & 15) * 136 + bCol) * 2);
    const unsigned int bLoAddr = smaddr(w_lo) + (unsigned)(((lane & 15) * 136 + bCol) * 2);

    float c_[2][8][4];
    #pragma unroll
    for (int mt = 0; mt < 2; ++mt)
        #pragma unroll
        for (int nt = 0; nt < 8; ++nt)
            #pragma unroll
            for (int i = 0; i < 4; ++i) c_[mt][nt][i] = 0.f;

    const int NT = K >> 4;
    uint4 rAh = *(const uint4*)pAh;
    uint4 rAl = *(const uint4*)pAl;
    uint4 rWh = *(const uint4*)pWh;
    uint4 rWl = *(const uint4*)pWl;

    for (int kt = 0; kt < NT; ++kt) {
        *(uint4*)(a_hi + ar * 24 + ak) = rAh;
        *(uint4*)(a_lo + ar * 24 + ak) = rAl;
        *(uint4*)(w_hi + wk * 136 + wc) = rWh;
        *(uint4*)(w_lo + wk * 136 + wc) = rWl;
        __syncthreads();

        if (kt + 1 < NT) {
            int k0 = (kt + 1) << 4;
            rAh = *(const uint4*)(pAh + k0);
            rAl = *(const uint4*)(pAl + k0);
            rWh = *(const uint4*)(pWh + (size_t)k0 * 1536);
            rWl = *(const uint4*)(pWl + (size_t)k0 * 1536);
        }

        unsigned int afh[2][4], afl[2][4];
        #pragma unroll
        for (int mt = 0; mt < 2; ++mt) {
            LDSM4(afh[mt], aHiAddr + mt * 768);
            LDSM4(afl[mt], aLoAddr + mt * 768);
        }

        #pragma unroll
        for (int p = 0; p < 4; ++p) {
            unsigned int bh[4], bl[4];
            LDSM4T(bh, bHiAddr + p * 32);
            LDSM4T(bl, bLoAddr + p * 32);
            #pragma unroll
            for (int s = 0; s < 2; ++s) {
                const int nt = 2 * p + s;
                #pragma unroll
                for (int mt = 0; mt < 2; ++mt) {
                    MMA_BF16(c_[mt][nt], afh[mt], bh[2 * s], bh[2 * s + 1]);
                    MMA_BF16(c_[mt][nt], afh[mt], bl[2 * s], bl[2 * s + 1]);
                    MMA_BF16(c_[mt][nt], afl[mt], bh[2 * s], bh[2 * s + 1]);
                }
            }
        }
        __syncthreads();
    }

    #pragma unroll
    for (int nt = 0; nt < 8; ++nt) {
        int col = n0 + warpN * 64 + nt * 8 + t4 * 2;
        float bx = __ldg(bias + col);
        float by = __ldg(bias + col + 1);
        #pragma unroll
        for (int mt = 0; mt < 2; ++mt) {
            int r = m0 + warpM * 32 + mt * 16 + g;
            float2 o0 = {c_[mt][nt][0] + bx, c_[mt][nt][1] + by};
            float2 o1 = {c_[mt][nt][2] + bx, c_[mt][nt][3] + by};
            *(float2*)(C + (size_t)r * 1536 + col)       = o0;
            *(float2*)(C + (size_t)(r + 8) * 1536 + col) = o1;
        }
    }
}

// ============================================================================
// Recurrence: k-split + PER-WARP dataflow.
//   Warp w consumes h cols [64w,64w+64) = output of producer CTAs 8w..8w+8.
//   Per step, warp w: polls ITS 8 producer flags -> stages ITS 8KB chunk ->
//   __syncwarp -> 16 LDSM + 72 mma -> partial store. ONE join __syncthreads
//   before the scalar epilogue; publish h + flag after.
//   Safety: all 8 warps jointly cover all 64 producers, so h-publish (after
//   the join) still orders after every CTA's step-t read of the parity buffer.
// SMEM: ahi[32][520] | alo[32][520] bf16 | part[8][3][256] f32 | hp[256]
// ============================================================================
#define LDK 520
#define REC_SMEM (2 * 32 * LDK * 2 + 8 * 3 * 256 * 4 + 256 * 4)

__global__ void __launch_bounds__(REC_THREADS, 1) gru_rec_kernel(
    const float* __restrict__ xzf, const float* __restrict__ xzb,
    const float* __restrict__ rkf, const float* __restrict__ rkb,
    const float* __restrict__ bf,  const float* __restrict__ bb,
    const unsigned char* __restrict__ mask,
    float* __restrict__ y32,
    __nv_bfloat16* __restrict__ yhi, __nv_bfloat16* __restrict__ ylo,
    unsigned char* __restrict__ nextmask,
    int T, int flagBase, int writeHidden, float* __restrict__ hiddenOut) {
    extern __shared__ __align__(16) char smraw[];
    __nv_bfloat16* sh_ahi = (__nv_bfloat16*)smraw;                // [32][520]
    __nv_bfloat16* sh_alo = sh_ahi + 32 * LDK;                    // [32][520]
    float* sh_part = (float*)(sh_alo + 32 * LDK);                 // [8][3][256]
    float* sh_hp   = sh_part + 8 * 3 * 256;                       // [256]

    const int tid  = threadIdx.x;
    const int lane = tid & 31, wid = tid >> 5;
    const int dir = blockIdx.x >> 6;
    const int j   = blockIdx.x & 63;
    const int cb  = j << 3;
    const int b   = tid >> 3;
    const int c8  = tid & 7;
    const int col = cb + c8;

    const float* xz = dir ? xzb : xzf;
    const float* rk = dir ? rkb : rkf;
    const float* bi = (dir ? bb : bf) + 1536;   // b[1]

    sh_hp[tid] = 0.f;

    // ---- B-fragment preload: warp w owns kt = 4w..4w+3, all 3 gates ----
    const int t4 = lane & 3;
    const int gcol = lane >> 2;
    unsigned int Bh0[3][4], Bh1[3][4], Bl0[3][4], Bl1[3][4];
    #pragma unroll 1
    for (int gate = 0; gate < 3; ++gate) {
        const float* wcolp = rk + gate * 512 + cb + gcol;
        #pragma unroll
        for (int q = 0; q < 4; ++q) {
            int k0 = (wid * 4 + q) * 16 + t4 * 2;
            float w00 = __ldg(wcolp + (size_t)(k0)     * 1536);
            float w01 = __ldg(wcolp + (size_t)(k0 + 1) * 1536);
            float w10 = __ldg(wcolp + (size_t)(k0 + 8) * 1536);
            float w11 = __ldg(wcolp + (size_t)(k0 + 9) * 1536);
            __nv_bfloat16 h00 = __float2bfloat16(w00), h01 = __float2bfloat16(w01);
            __nv_bfloat16 h10 = __float2bfloat16(w10), h11 = __float2bfloat16(w11);
            Bh0[gate][q] = ((unsigned)*(unsigned short*)&h01 << 16) | *(unsigned short*)&h00;
            Bh1[gate][q] = ((unsigned)*(unsigned short*)&h11 << 16) | *(unsigned short*)&h10;
            Bl0[gate][q] = bfpack(w00 - __bfloat162float(h00), w01 - __bfloat162float(h01));
            Bl1[gate][q] = bfpack(w10 - __bfloat162float(h10), w11 - __bfloat162float(h11));
        }
    }
    const float bz = __ldg(bi + col);
    const float br = __ldg(bi + 512 + col);
    const float bh = __ldg(bi + 1024 + col);
    __syncthreads();

    // ldmatrix bases: warp reads only its own staged 64-col chunk
    const unsigned int aB0 = smaddr(sh_ahi) +
        (unsigned)((((lane & 15)) * LDK + ((lane >> 4) << 3)) * 2) + (unsigned)(wid * 128);
    const unsigned int aB1 = aB0 + (unsigned)(16 * LDK * 2);
    const unsigned int loOfs = (unsigned)(32 * LDK * 2);

    unsigned int* myflag = g_flag + dir * 512 + j * 8;
    // warp w polls producer CTAs 8w..8w+8 (lane&7 selects one; redundant x4)
    const unsigned int* pollflag = g_flag + dir * 512 + (wid * 8 + (lane & 7)) * 8;
    const bool maskWriter = (nextmask != nullptr) && (dir == 0) && (j == 0) && (c8 == 0);
    unsigned char mprev = 0;

    for (int t = 0; t < T; ++t) {
        const int tsrc = dir ? (T - 1 - t) : t;
        const size_t xoff = ((size_t)b * T + t) * 1536;
        const float x0 = __ldg(xz + xoff + col);
        const float x1 = __ldg(xz + xoff + 512 + col);
        const float x2 = __ldg(xz + xoff + 1024 + col);
        const unsigned char m = mask[b * T + tsrc];

        if (t > 0) {
            // ---- per-warp: wait for THIS warp's 8 producer CTAs ----
            {
                const unsigned int target = (unsigned int)(flagBase + t);
                unsigned int v;
                do {
                    asm volatile("ld.acquire.gpu.global.u32 %0, [%1];"
                                 : "=r"(v) : "l"(pollflag) : "memory");
                } while (__any_sync(0xffffffffu, v < target));
            }

            // ---- per-warp: stage own 64-col chunk (hi+lo, 8KB) ----
            const size_t hsrc = (size_t)(((t & 1) * 2 + dir)) << 14;
            const __nv_bfloat16* ghi = g_hhi + hsrc + wid * 64;
            const __nv_bfloat16* glo = g_hlo + hsrc + wid * 64;
            uint4 hv[8], lv[8];
            #pragma unroll
            for (int q = 0; q < 8; ++q) {
                int v = q * 32 + lane;          // 0..255
                int bb2 = v >> 3, kc = v & 7;   // row 0..31, col-chunk 0..7
                hv[q] = __ldcg((const uint4*)(ghi + (bb2 << 9) + kc * 8));
                lv[q] = __ldcg((const uint4*)(glo + (bb2 << 9) + kc * 8));
            }
            #pragma unroll
            for (int q = 0; q < 8; ++q) {
                int v = q * 32 + lane;
                int bb2 = v >> 3, kc = v & 7;
                *(uint4*)(sh_ahi + bb2 * LDK + wid * 64 + kc * 8) = hv[q];
                *(uint4*)(sh_alo + bb2 * LDK + wid * 64 + kc * 8) = lv[q];
            }
            __syncwarp();

            // ---- per-warp mma: 4 kt x (4 LDSM + 18 mma) ----
            float acc[3][2][4];
            #pragma unroll
            for (int gg = 0; gg < 3; ++gg)
                #pragma unroll
                for (int mt = 0; mt < 2; ++mt)
                    #pragma unroll
                    for (int i = 0; i < 4; ++i) acc[gg][mt][i] = 0.f;

            #pragma unroll
            for (int q = 0; q < 4; ++q) {
                unsigned int ah[2][4], al[2][4];
                LDSM4(ah[0], aB0 + q * 32);
                LDSM4(ah[1], aB1 + q * 32);
                LDSM4(al[0], aB0 + loOfs + q * 32);
                LDSM4(al[1], aB1 + loOfs + q * 32);
                #pragma unroll
                for (int gg = 0; gg < 3; ++gg) {
                    #pragma unroll
                    for (int mt = 0; mt < 2; ++mt) {
                        MMA_BF16(acc[gg][mt], ah[mt], Bh0[gg][q], Bh1[gg][q]);
                        MMA_BF16(acc[gg][mt], ah[mt], Bl0[gg][q], Bl1[gg][q]);
                        MMA_BF16(acc[gg][mt], al[mt], Bh0[gg][q], Bh1[gg][q]);
                    }
                }
            }
            const int row = lane >> 2, cq = (lane & 3) << 1;
            #pragma unroll
            for (int gg = 0; gg < 3; ++gg) {
                #pragma unroll
                for (int mt = 0; mt < 2; ++mt) {
                    float* gp = sh_part + (wid * 3 + gg) * 256 + (mt * 16 + row) * 8 + cq;
                    gp[0]  = acc[gg][mt][0];
                    gp[1]  = acc[gg][mt][1];
                    gp[64] = acc[gg][mt][2];
                    gp[65] = acc[gg][mt][3];
                }
            }
            __syncthreads();   // join: all partials visible (covers all 64 producers)
        }

        // ---- scalar epilogue: reduce 8 partials per gate ----
        float iz = bz, ir = br, ic = bh;
        if (t > 0) {
            #pragma unroll
            for (int w = 0; w < 8; ++w) {
                iz += sh_part[(w * 3 + 0) * 256 + tid];
                ir += sh_part[(w * 3 + 1) * 256 + tid];
                ic += sh_part[(w * 3 + 2) * 256 + tid];
            }
        }

        const float zg = 1.f / (1.f + expf(-(x0 + iz)));
        const float rg = 1.f / (1.f + expf(-(x1 + ir)));
        const float hh = tanhf(x2 + rg * ic);
        const float hp = sh_hp[tid];
        const float hn = zg * hp + (1.f - zg) * hh;
        const float hsel = m ? hn : hp;
        const float yval = m ? hn : 0.f;
        sh_hp[tid] = hsel;

        // ---- critical path: publish h (bf16 hi/lo) + flag ----
        const size_t hdst = (size_t)((((t + 1) & 1) * 2 + dir)) << 14;
        __nv_bfloat16 h16 = __float2bfloat16(hsel);
        __nv_bfloat16 l16 = __float2bfloat16(hsel - __bfloat162float(h16));
        g_hhi[hdst + (b << 9) + col] = h16;
        g_hlo[hdst + (b << 9) + col] = l16;
        __syncthreads();
        if (tid == 0) {
            unsigned int v = (unsigned int)(flagBase + t + 1);
            asm volatile("st.release.gpu.global.u32 [%0], %1;"
                         :: "l"(myflag), "r"(v) : "memory");
        }

        // ---- off critical path: outputs ----
        const size_t yidx = ((size_t)b * T + tsrc) * 1024 + (dir << 9) + col;
        if (yhi) {
            __nv_bfloat16 yh16 = __float2bfloat16(yval);
            yhi[yidx] = yh16;
            ylo[yidx] = __float2bfloat16(yval - __bfloat162float(yh16));
        }
        if (y32) y32[yidx] = yval;
        if (writeHidden && t == T - 1)
            hiddenOut[(b << 10) + (dir << 9) + col] = hsel;
        if (maskWriter) {
            if ((t & 1) == 0) mprev = m;
            else nextmask[b * (T >> 1) + (t >> 1)] = (unsigned char)(mprev | m);
        }
    }
}

// ============================================================================
// Launch sequence (graph-capturable)
// ============================================================================
extern "C" void kernel_launch(void* const* d_in, const int* in_sizes, int n_in,
                              void* d_out, int out_size) {
    (void)in_sizes; (void)n_in; (void)out_size;
    const float* inputs = (const float*)d_in[0];

    const float *k_[4][2], *r_[4][2], *bi_[4][2];
    for (int l = 0; l < 4; ++l)
        for (int d = 0; d < 2; ++d) {
            int base = 3 + l * 6 + d * 3;
            k_[l][d]  = (const float*)d_in[base + 0];
            r_[l][d]  = (const float*)d_in[base + 1];
            bi_[l][d] = (const float*)d_in[base + 2];
        }

    float *xzf, *xzb;
    unsigned char* mk;
    __nv_bfloat16 *whi, *wlo, *inhi, *inlo, *yh0, *yl0, *yh1, *yl1;
    cudaGetSymbolAddress((void**)&xzf, g_xzf);
    cudaGetSymbolAddress((void**)&xzb, g_xzb);
    cudaGetSymbolAddress((void**)&mk, g_mask);
    cudaGetSymbolAddress((void**)&whi, g_whi);
    cudaGetSymbolAddress((void**)&wlo, g_wlo);
    cudaGetSymbolAddress((void**)&inhi, g_inhi);
    cudaGetSymbolAddress((void**)&inlo, g_inlo);
    cudaGetSymbolAddress((void**)&yh0, g_yh0);
    cudaGetSymbolAddress((void**)&yl0, g_yl0);
    cudaGetSymbolAddress((void**)&yh1, g_yh1);
    cudaGetSymbolAddress((void**)&yl1, g_yl1);

    cudaFuncSetAttribute(gru_rec_kernel,
                         cudaFuncAttributeMaxDynamicSharedMemorySize, REC_SMEM);

    float* outp = (float*)d_out;
    float* hid  = outp + (size_t)32 * 128 * 1024;

    prep_kernel<<<2048, 256>>>(inputs, k_[0][0], k_[0][1], k_[1][0], k_[1][1],
                               k_[2][0], k_[2][1], k_[3][0], k_[3][1]);

    const int Ts[4]   = {1024, 512, 256, 128};
    const int Ks[4]   = {240, 2048, 2048, 2048};
    const int ldas[4] = {240, 2048, 2048, 2048};
    const int woff[4][2] = {{0, WSZ0},
                            {2 * WSZ0, 2 * WSZ0 + WSZ1},
                            {2 * WSZ0 + 2 * WSZ1, 2 * WSZ0 + 3 * WSZ1},
                            {2 * WSZ0 + 4 * WSZ1, 2 * WSZ0 + 5 * WSZ1}};
    const int moff[4]  = {0, 32768, 49152, 57344};
    const int fbase[4] = {0, 1024, 1536, 1792};

    const __nv_bfloat16* Ah[4] = {inhi, yh0, yh1, yh0};
    const __nv_bfloat16* Al[4] = {inlo, yl0, yl1, yl0};
    __nv_bfloat16* Yh[4] = {yh0, yh1, yh0, nullptr};
    __nv_bfloat16* Yl[4] = {yl0, yl1, yl0, nullptr};
    float* Y32[4] = {nullptr, nullptr, nullptr, outp};

    for (int l = 0; l < 4; ++l) {
        const int T = Ts[l], K = Ks[l];
        const int rows = 32 * T;

        dim3 grid(12, rows / 128, 2);
        gemm_xz<<<grid, 256>>>(Ah[l], Al[l], ldas[l],
                               whi + woff[l][0], wlo + woff[l][0],
                               whi + woff[l][1], wlo + woff[l][1],
                               bi_[l][0], bi_[l][1],
                               xzf, xzb, K, T, mk + moff[l]);

        gru_rec_kernel<<<128, REC_THREADS, REC_SMEM>>>(
            xzf, xzb, r_[l][0], r_[l][1], bi_[l][0], bi_[l][1],
            mk + moff[l], Y32[l], Yh[l], Yl[l],
            (l < 3) ? (mk + moff[l + 1]) : nullptr,
            T, fbase[l], (l == 3) ? 1 : 0, hid);
    }
}

// round 14
// speedup vs baseline: 1.2049x; 1.1263x over previous
#include <cuda_runtime.h>
#include <cuda_bf16.h>
#include <cuda_fp16.h>
#include <cstdint>

// ============================================================================
// 4-layer pyramidal BiGRU. B=32, H=512, 3H=1536.
// Layers l=0..3: T = 1024,512,256,128 ; din = 240,2048,2048,2048
// ============================================================================

#define REC_THREADS 256

// ---------------- static device scratch ----------------
__device__ float g_xzf[50331648];                 // [32][1024][1536] max
__device__ float g_xzb[50331648];
__device__ unsigned int g_flag[2 * 512];          // [dir][64 ctas] stride-8
__device__ unsigned char g_mask[65536];           // per-layer offsets
__device__ __nv_bfloat16 g_whi[19611648], g_wlo[19611648];
__device__ __nv_bfloat16 g_inhi[7864320],  g_inlo[7864320];
__device__ __nv_bfloat16 g_yh0[33554432],  g_yl0[33554432];
__device__ __nv_bfloat16 g_yh1[16777216],  g_yl1[16777216];
__device__ __half g_hh[4 * 16384];                // [parity][dir][32][512] fp16

// ---------------- mma / ldmatrix ----------------
#define MMA_BF16(c, a, b0, b1)                                              \
    asm volatile("mma.sync.aligned.m16n8k16.row.col.f32.bf16.bf16.f32 "     \
        "{%0,%1,%2,%3}, {%4,%5,%6,%7}, {%8,%9}, {%0,%1,%2,%3};"             \
        : "+f"((c)[0]), "+f"((c)[1]), "+f"((c)[2]), "+f"((c)[3])            \
        : "r"((a)[0]), "r"((a)[1]), "r"((a)[2]), "r"((a)[3]),               \
          "r"(b0), "r"(b1))

#define MMA_F16(c, a, b0, b1)                                               \
    asm volatile("mma.sync.aligned.m16n8k16.row.col.f32.f16.f16.f32 "       \
        "{%0,%1,%2,%3}, {%4,%5,%6,%7}, {%8,%9}, {%0,%1,%2,%3};"             \
        : "+f"((c)[0]), "+f"((c)[1]), "+f"((c)[2]), "+f"((c)[3])            \
        : "r"((a)[0]), "r"((a)[1]), "r"((a)[2]), "r"((a)[3]),               \
          "r"(b0), "r"(b1))

#define LDSM4(R, addr)                                                      \
    asm volatile("ldmatrix.sync.aligned.m8n8.x4.shared.b16 "                \
        "{%0,%1,%2,%3}, [%4];"                                              \
        : "=r"((R)[0]), "=r"((R)[1]), "=r"((R)[2]), "=r"((R)[3])            \
        : "r"(addr))

#define LDSM4T(R, addr)                                                     \
    asm volatile("ldmatrix.sync.aligned.m8n8.x4.trans.shared.b16 "          \
        "{%0,%1,%2,%3}, [%4];"                                              \
        : "=r"((R)[0]), "=r"((R)[1]), "=r"((R)[2]), "=r"((R)[3])            \
        : "r"(addr))

__device__ __forceinline__ unsigned int smaddr(const void* p) {
    return (unsigned int)__cvta_generic_to_shared(p);
}
__device__ __forceinline__ unsigned int h2pack(float a, float b) {
    __half2 h = __floats2half2_rn(a, b);
    return *reinterpret_cast<unsigned int*>(&h);
}

// ============================================================================
// prep kernel: convert 8 weight matrices + layer-0 input to bf16 hi/lo,
// compute layer-0 mask, zero flags. (unchanged)
// ============================================================================
__device__ __forceinline__ void cvt4(float4 v, uint2& hi, uint2& lo) {
    __nv_bfloat162 h0 = __floats2bfloat162_rn(v.x, v.y);
    __nv_bfloat162 h1 = __floats2bfloat162_rn(v.z, v.w);
    float2 f0 = __bfloat1622float2(h0);
    float2 f1 = __bfloat1622float2(h1);
    __nv_bfloat162 l0 = __floats2bfloat162_rn(v.x - f0.x, v.y - f0.y);
    __nv_bfloat162 l1 = __floats2bfloat162_rn(v.z - f1.x, v.w - f1.y);
    hi.x = *(unsigned int*)&h0; hi.y = *(unsigned int*)&h1;
    lo.x = *(unsigned int*)&l0; lo.y = *(unsigned int*)&l1;
}

#define WSZ0 368640
#define WSZ1 3145728

__global__ void prep_kernel(const float* __restrict__ in,
                            const float* w0, const float* w1, const float* w2,
                            const float* w3, const float* w4, const float* w5,
                            const float* w6, const float* w7) {
    const float* ws[8] = {w0, w1, w2, w3, w4, w5, w6, w7};
    const int sz[8]  = {WSZ0, WSZ0, WSZ1, WSZ1, WSZ1, WSZ1, WSZ1, WSZ1};
    const int off[8] = {0, WSZ0, 2 * WSZ0, 2 * WSZ0 + WSZ1, 2 * WSZ0 + 2 * WSZ1,
                        2 * WSZ0 + 3 * WSZ1, 2 * WSZ0 + 4 * WSZ1, 2 * WSZ0 + 5 * WSZ1};
    const int gid = blockIdx.x * blockDim.x + threadIdx.x;
    const int stride = gridDim.x * blockDim.x;

    #pragma unroll 1
    for (int w = 0; w < 8; ++w) {
        const float4* W = (const float4*)ws[w];
        uint2* hi = (uint2*)(g_whi + off[w]);
        uint2* lo = (uint2*)(g_wlo + off[w]);
        int n4 = sz[w] >> 2;
        for (int i = gid; i < n4; i += stride) {
            uint2 h, l; cvt4(__ldg(W + i), h, l);
            hi[i] = h; lo[i] = l;
        }
    }
    {
        const float4* X = (const float4*)in;
        uint2* hi = (uint2*)g_inhi; uint2* lo = (uint2*)g_inlo;
        for (int i = gid; i < (7864320 >> 2); i += stride) {
            uint2 h, l; cvt4(__ldg(X + i), h, l);
            hi[i] = h; lo[i] = l;
        }
    }
    for (int r = gid; r < 32768; r += stride) {
        const float4* p = (const float4*)(in + (size_t)r * 240);
        bool any = false;
        for (int i = 0; i < 60; ++i) {
            float4 v = __ldg(p + i);
            any = any | (v.x != 0.f) | (v.y != 0.f) | (v.z != 0.f) | (v.w != 0.f);
            if (any) break;
        }
        g_mask[r] = any ? 1 : 0;
    }
    for (int i = gid; i < 2 * 512; i += stride) g_flag[i] = 0u;
}

// ============================================================================
// Input-projection GEMM — EXACT round-11/13 version (proven best):
// bf16 hi/lo, mma.sync, tile 128x128x16, 2 CTAs/SM, masked-tile skip.
// ============================================================================
__global__ void __launch_bounds__(256, 2) gemm_xz(
    const __nv_bfloat16* __restrict__ Ahi, const __nv_bfloat16* __restrict__ Alo,
    int lda,
    const __nv_bfloat16* __restrict__ WhiF, const __nv_bfloat16* __restrict__ WloF,
    const __nv_bfloat16* __restrict__ WhiB, const __nv_bfloat16* __restrict__ WloB,
    const float* __restrict__ biasF, const float* __restrict__ biasB,
    float* __restrict__ Cf, float* __restrict__ Cb,
    int K, int Tcur, const unsigned char* __restrict__ mask) {
    __shared__ __align__(16) __nv_bfloat16 a_hi[128 * 24], a_lo[128 * 24];
    __shared__ __align__(16) __nv_bfloat16 w_hi[16 * 136], w_lo[16 * 136];

    const int dir = blockIdx.z;
    const int rev = dir;
    const __nv_bfloat16* Whi = dir ? WhiB : WhiF;
    const __nv_bfloat16* Wlo = dir ? WloB : WloF;
    const float* bias = dir ? biasB : biasF;
    float* C = dir ? Cb : Cf;

    const int tid  = threadIdx.x;
    const int lane = tid & 31, wid = tid >> 5;
    const int g = lane >> 2, t4 = lane & 3;
    const int warpM = wid & 3, warpN = wid >> 2;
    const int m0 = blockIdx.y << 7, n0 = blockIdx.x << 7;

    {
        const int b  = m0 / Tcur;
        const int t0 = m0 - b * Tcur;
        const int ttmin = rev ? (Tcur - 128 - t0) : t0;
        if (mask[b * Tcur + ttmin] == 0) return;
    }

    const int ar = tid >> 1;
    const int ak = (tid & 1) << 3;
    const int wk = tid >> 4;
    const int wc = (tid & 15) << 3;

    const __nv_bfloat16 *pAh, *pAl;
    {
        int m  = m0 + ar;
        int bi = m / Tcur;
        int t  = m - bi * Tcur;
        int tt = rev ? (Tcur - 1 - t) : t;
        size_t base = ((size_t)bi * Tcur + tt) * lda + ak;
        pAh = Ahi + base; pAl = Alo + base;
    }
    const __nv_bfloat16* pWh = Whi + (size_t)wk * 1536 + n0 + wc;
    const __nv_bfloat16* pWl = Wlo + (size_t)wk * 1536 + n0 + wc;

    const int aRowL = warpM * 32 + (lane & 15);
    const int aKofL = (lane & 16) >> 1;
    const unsigned int aHiAddr = smaddr(a_hi) + (unsigned)((aRowL * 24 + aKofL) * 2);
    const unsigned int aLoAddr = smaddr(a_lo) + (unsigned)((aRowL * 24 + aKofL) * 2);
    const int bCol = warpN * 64 + ((lane & 16) >> 1);
    const unsigned int bHiAddr = smaddr(w_hi) + (unsigned)(((lane & 15) * 136 + bCol) * 2);
    const unsigned int bLoAddr = smaddr(w_lo) + (unsigned)(((lane & 15) * 136 + bCol) * 2);

    float c_[2][8][4];
    #pragma unroll
    for (int mt = 0; mt < 2; ++mt)
        #pragma unroll
        for (int nt = 0; nt < 8; ++nt)
            #pragma unroll
            for (int i = 0; i < 4; ++i) c_[mt][nt][i] = 0.f;

    const int NT = K >> 4;
    uint4 rAh = *(const uint4*)pAh;
    uint4 rAl = *(const uint4*)pAl;
    uint4 rWh = *(const uint4*)pWh;
    uint4 rWl = *(const uint4*)pWl;

    for (int kt = 0; kt < NT; ++kt) {
        *(uint4*)(a_hi + ar * 24 + ak) = rAh;
        *(uint4*)(a_lo + ar * 24 + ak) = rAl;
        *(uint4*)(w_hi + wk * 136 + wc) = rWh;
        *(uint4*)(w_lo + wk * 136 + wc) = rWl;
        __syncthreads();

        if (kt + 1 < NT) {
            int k0 = (kt + 1) << 4;
            rAh = *(const uint4*)(pAh + k0);
            rAl = *(const uint4*)(pAl + k0);
            rWh = *(const uint4*)(pWh + (size_t)k0 * 1536);
            rWl = *(const uint4*)(pWl + (size_t)k0 * 1536);
        }

        unsigned int afh[2][4], afl[2][4];
        #pragma unroll
        for (int mt = 0; mt < 2; ++mt) {
            LDSM4(afh[mt], aHiAddr + mt * 768);
            LDSM4(afl[mt], aLoAddr + mt * 768);
        }

        #pragma unroll
        for (int p = 0; p < 4; ++p) {
            unsigned int bh[4], bl[4];
            LDSM4T(bh, bHiAddr + p * 32);
            LDSM4T(bl, bLoAddr + p * 32);
            #pragma unroll
            for (int s = 0; s < 2; ++s) {
                const int nt = 2 * p + s;
                #pragma unroll
                for (int mt = 0; mt < 2; ++mt) {
                    MMA_BF16(c_[mt][nt], afh[mt], bh[2 * s], bh[2 * s + 1]);
                    MMA_BF16(c_[mt][nt], afh[mt], bl[2 * s], bl[2 * s + 1]);
                    MMA_BF16(c_[mt][nt], afl[mt], bh[2 * s], bh[2 * s + 1]);
                }
            }
        }
        __syncthreads();
    }

    #pragma unroll
    for (int nt = 0; nt < 8; ++nt) {
        int col = n0 + warpN * 64 + nt * 8 + t4 * 2;
        float bx = __ldg(bias + col);
        float by = __ldg(bias + col + 1);
        #pragma unroll
        for (int mt = 0; mt < 2; ++mt) {
            int r = m0 + warpM * 32 + mt * 16 + g;
            float2 o0 = {c_[mt][nt][0] + bx, c_[mt][nt][1] + by};
            float2 o1 = {c_[mt][nt][2] + bx, c_[mt][nt][3] + by};
            *(float2*)(C + (size_t)r * 1536 + col)       = o0;
            *(float2*)(C + (size_t)(r + 8) * 1536 + col) = o1;
        }
    }
}

// ============================================================================
// Recurrence: per-warp dataflow (round-13) + FP16 2-term math.
//   h is bounded [-1,1] -> published as SINGLE fp16 (no lo split).
//   W in fp16 hi+lo (exact to 2^-22). inner = h_f16 x (W_hi + W_lo): 2 mma
//   terms instead of 3; h staging/LDSM traffic halves; publish is 1 store.
//   Warp w: polls its 8 producers -> stages own 64-col fp16 chunk (4KB) ->
//   16 LDSM.x4 + 48 mma -> partial store -> join -> scalar epilogue (fp32
//   carry stays exact in SMEM).
// SMEM: ah[32][520] fp16 | part[8][3][256] f32 | hp[256] f32
// ============================================================================
#define LDK 520
#define REC_SMEM (32 * LDK * 2 + 8 * 3 * 256 * 4 + 256 * 4)

__global__ void __launch_bounds__(REC_THREADS, 1) gru_rec_kernel(
    const float* __restrict__ xzf, const float* __restrict__ xzb,
    const float* __restrict__ rkf, const float* __restrict__ rkb,
    const float* __restrict__ bf,  const float* __restrict__ bb,
    const unsigned char* __restrict__ mask,
    float* __restrict__ y32,
    __nv_bfloat16* __restrict__ yhi, __nv_bfloat16* __restrict__ ylo,
    unsigned char* __restrict__ nextmask,
    int T, int flagBase, int writeHidden, float* __restrict__ hiddenOut) {
    extern __shared__ __align__(16) char smraw[];
    __half* sh_ah = (__half*)smraw;                       // [32][520]
    float* sh_part = (float*)(sh_ah + 32 * LDK);          // [8][3][256]
    float* sh_hp   = sh_part + 8 * 3 * 256;               // [256]

    const int tid  = threadIdx.x;
    const int lane = tid & 31, wid = tid >> 5;
    const int dir = blockIdx.x >> 6;
    const int j   = blockIdx.x & 63;
    const int cb  = j << 3;
    const int b   = tid >> 3;
    const int c8  = tid & 7;
    const int col = cb + c8;

    const float* xz = dir ? xzb : xzf;
    const float* rk = dir ? rkb : rkf;
    const float* bi = (dir ? bb : bf) + 1536;   // b[1]

    sh_hp[tid] = 0.f;

    // ---- B-fragment preload (fp16 hi/lo): warp w owns kt = 4w..4w+3 ----
    const int t4 = lane & 3;
    const int gcol = lane >> 2;
    unsigned int Bh0[3][4], Bh1[3][4], Bl0[3][4], Bl1[3][4];
    #pragma unroll 1
    for (int gate = 0; gate < 3; ++gate) {
        const float* wcolp = rk + gate * 512 + cb + gcol;
        #pragma unroll
        for (int q = 0; q < 4; ++q) {
            int k0 = (wid * 4 + q) * 16 + t4 * 2;
            float w00 = __ldg(wcolp + (size_t)(k0)     * 1536);
            float w01 = __ldg(wcolp + (size_t)(k0 + 1) * 1536);
            float w10 = __ldg(wcolp + (size_t)(k0 + 8) * 1536);
            float w11 = __ldg(wcolp + (size_t)(k0 + 9) * 1536);
            __half h00 = __float2half_rn(w00), h01 = __float2half_rn(w01);
            __half h10 = __float2half_rn(w10), h11 = __float2half_rn(w11);
            Bh0[gate][q] = ((unsigned)*(unsigned short*)&h01 << 16) | *(unsigned short*)&h00;
            Bh1[gate][q] = ((unsigned)*(unsigned short*)&h11 << 16) | *(unsigned short*)&h10;
            Bl0[gate][q] = h2pack(w00 - __half2float(h00), w01 - __half2float(h01));
            Bl1[gate][q] = h2pack(w10 - __half2float(h10), w11 - __half2float(h11));
        }
    }
    const float bz = __ldg(bi + col);
    const float br = __ldg(bi + 512 + col);
    const float bh = __ldg(bi + 1024 + col);
    __syncthreads();

    // ldmatrix base: warp reads only its own staged 64-col chunk
    const unsigned int aB0 = smaddr(sh_ah) +
        (unsigned)((((lane & 15)) * LDK + ((lane >> 4) << 3)) * 2) + (unsigned)(wid * 128);
    const unsigned int aB1 = aB0 + (unsigned)(16 * LDK * 2);

    unsigned int* myflag = g_flag + dir * 512 + j * 8;
    const unsigned int* pollflag = g_flag + dir * 512 + (wid * 8 + (lane & 7)) * 8;
    const bool maskWriter = (nextmask != nullptr) && (dir == 0) && (j == 0) && (c8 == 0);
    unsigned char mprev = 0;

    for (int t = 0; t < T; ++t) {
        const int tsrc = dir ? (T - 1 - t) : t;
        const size_t xoff = ((size_t)b * T + t) * 1536;
        const float x0 = __ldg(xz + xoff + col);
        const float x1 = __ldg(xz + xoff + 512 + col);
        const float x2 = __ldg(xz + xoff + 1024 + col);
        const unsigned char m = mask[b * T + tsrc];

        if (t > 0) {
            // ---- per-warp: wait for THIS warp's 8 producer CTAs ----
            {
                const unsigned int target = (unsigned int)(flagBase + t);
                unsigned int v;
                do {
                    asm volatile("ld.acquire.gpu.global.u32 %0, [%1];"
                                 : "=r"(v) : "l"(pollflag) : "memory");
                } while (__any_sync(0xffffffffu, v < target));
            }

            // ---- per-warp: stage own 64-col fp16 chunk (4KB) ----
            const size_t hsrc = (size_t)(((t & 1) * 2 + dir)) << 14;
            const __half* gh = g_hh + hsrc + wid * 64;
            uint4 hv[8];
            #pragma unroll
            for (int q = 0; q < 8; ++q) {
                int v = q * 32 + lane;          // 0..255
                int bb2 = v >> 3, kc = v & 7;   // row 0..31, 8-half chunk
                hv[q] = __ldcg((const uint4*)(gh + (bb2 << 9) + kc * 8));
            }
            #pragma unroll
            for (int q = 0; q < 8; ++q) {
                int v = q * 32 + lane;
                int bb2 = v >> 3, kc = v & 7;
                *(uint4*)(sh_ah + bb2 * LDK + wid * 64 + kc * 8) = hv[q];
            }
            __syncwarp();

            // ---- per-warp mma: 4 kt x (2 LDSM + 12 mma) ----
            float acc[3][2][4];
            #pragma unroll
            for (int gg = 0; gg < 3; ++gg)
                #pragma unroll
                for (int mt = 0; mt < 2; ++mt)
                    #pragma unroll
                    for (int i = 0; i < 4; ++i) acc[gg][mt][i] = 0.f;

            #pragma unroll
            for (int q = 0; q < 4; ++q) {
                unsigned int ah[2][4];
                LDSM4(ah[0], aB0 + q * 32);
                LDSM4(ah[1], aB1 + q * 32);
                #pragma unroll
                for (int gg = 0; gg < 3; ++gg) {
                    #pragma unroll
                    for (int mt = 0; mt < 2; ++mt) {
                        MMA_F16(acc[gg][mt], ah[mt], Bh0[gg][q], Bh1[gg][q]);
                        MMA_F16(acc[gg][mt], ah[mt], Bl0[gg][q], Bl1[gg][q]);
                    }
                }
            }
            const int row = lane >> 2, cq = (lane & 3) << 1;
            #pragma unroll
            for (int gg = 0; gg < 3; ++gg) {
                #pragma unroll
                for (int mt = 0; mt < 2; ++mt) {
                    float* gp = sh_part + (wid * 3 + gg) * 256 + (mt * 16 + row) * 8 + cq;
                    gp[0]  = acc[gg][mt][0];
                    gp[1]  = acc[gg][mt][1];
                    gp[64] = acc[gg][mt][2];
                    gp[65] = acc[gg][mt][3];
                }
            }
            __syncthreads();   // join: all partials visible (covers all 64 producers)
        }

        // ---- scalar epilogue: reduce 8 partials per gate ----
        float iz = bz, ir = br, ic = bh;
        if (t > 0) {
            #pragma unroll
            for (int w = 0; w < 8; ++w) {
                iz += sh_part[(w * 3 + 0) * 256 + tid];
                ir += sh_part[(w * 3 + 1) * 256 + tid];
                ic += sh_part[(w * 3 + 2) * 256 + tid];
            }
        }

        const float zg = 1.f / (1.f + expf(-(x0 + iz)));
        const float rg = 1.f / (1.f + expf(-(x1 + ir)));
        const float hh = tanhf(x2 + rg * ic);
        const float hp = sh_hp[tid];
        const float hn = zg * hp + (1.f - zg) * hh;
        const float hsel = m ? hn : hp;
        const float yval = m ? hn : 0.f;
        sh_hp[tid] = hsel;

        // ---- critical path: publish h (single fp16) + flag ----
        const size_t hdst = (size_t)((((t + 1) & 1) * 2 + dir)) << 14;
        g_hh[hdst + (b << 9) + col] = __float2half_rn(hsel);
        __syncthreads();
        if (tid == 0) {
            unsigned int v = (unsigned int)(flagBase + t + 1);
            asm volatile("st.release.gpu.global.u32 [%0], %1;"
                         :: "l"(myflag), "r"(v) : "memory");
        }

        // ---- off critical path: outputs ----
        const size_t yidx = ((size_t)b * T + tsrc) * 1024 + (dir << 9) + col;
        if (yhi) {
            __nv_bfloat16 yh16 = __float2bfloat16(yval);
            yhi[yidx] = yh16;
            ylo[yidx] = __float2bfloat16(yval - __bfloat162float(yh16));
        }
        if (y32) y32[yidx] = yval;
        if (writeHidden && t == T - 1)
            hiddenOut[(b << 10) + (dir << 9) + col] = hsel;
        if (maskWriter) {
            if ((t & 1) == 0) mprev = m;
            else nextmask[b * (T >> 1) + (t >> 1)] = (unsigned char)(mprev | m);
        }
    }
}

// ============================================================================
// Launch sequence (graph-capturable)
// ============================================================================
extern "C" void kernel_launch(void* const* d_in, const int* in_sizes, int n_in,
                              void* d_out, int out_size) {
    (void)in_sizes; (void)n_in; (void)out_size;
    const float* inputs = (const float*)d_in[0];

    const float *k_[4][2], *r_[4][2], *bi_[4][2];
    for (int l = 0; l < 4; ++l)
        for (int d = 0; d < 2; ++d) {
            int base = 3 + l * 6 + d * 3;
            k_[l][d]  = (const float*)d_in[base + 0];
            r_[l][d]  = (const float*)d_in[base + 1];
            bi_[l][d] = (const float*)d_in[base + 2];
        }

    float *xzf, *xzb;
    unsigned char* mk;
    __nv_bfloat16 *whi, *wlo, *inhi, *inlo, *yh0, *yl0, *yh1, *yl1;
    cudaGetSymbolAddress((void**)&xzf, g_xzf);
    cudaGetSymbolAddress((void**)&xzb, g_xzb);
    cudaGetSymbolAddress((void**)&mk, g_mask);
    cudaGetSymbolAddress((void**)&whi, g_whi);
    cudaGetSymbolAddress((void**)&wlo, g_wlo);
    cudaGetSymbolAddress((void**)&inhi, g_inhi);
    cudaGetSymbolAddress((void**)&inlo, g_inlo);
    cudaGetSymbolAddress((void**)&yh0, g_yh0);
    cudaGetSymbolAddress((void**)&yl0, g_yl0);
    cudaGetSymbolAddress((void**)&yh1, g_yh1);
    cudaGetSymbolAddress((void**)&yl1, g_yl1);

    cudaFuncSetAttribute(gru_rec_kernel,
                         cudaFuncAttributeMaxDynamicSharedMemorySize, REC_SMEM);

    float* outp = (float*)d_out;
    float* hid  = outp + (size_t)32 * 128 * 1024;

    prep_kernel<<<2048, 256>>>(inputs, k_[0][0], k_[0][1], k_[1][0], k_[1][1],
                               k_[2][0], k_[2][1], k_[3][0], k_[3][1]);

    const int Ts[4]   = {1024, 512, 256, 128};
    const int Ks[4]   = {240, 2048, 2048, 2048};
    const int ldas[4] = {240, 2048, 2048, 2048};
    const int woff[4][2] = {{0, WSZ0},
                            {2 * WSZ0, 2 * WSZ0 + WSZ1},
                            {2 * WSZ0 + 2 * WSZ1, 2 * WSZ0 + 3 * WSZ1},
                            {2 * WSZ0 + 4 * WSZ1, 2 * WSZ0 + 5 * WSZ1}};
    const int moff[4]  = {0, 32768, 49152, 57344};
    const int fbase[4] = {0, 1024, 1536, 1792};

    const __nv_bfloat16* Ah[4] = {inhi, yh0, yh1, yh0};
    const __nv_bfloat16* Al[4] = {inlo, yl0, yl1, yl0};
    __nv_bfloat16* Yh[4] = {yh0, yh1, yh0, nullptr};
    __nv_bfloat16* Yl[4] = {yl0, yl1, yl0, nullptr};
    float* Y32[4] = {nullptr, nullptr, nullptr, outp};

    for (int l = 0; l < 4; ++l) {
        const int T = Ts[l], K = Ks[l];
        const int rows = 32 * T;

        dim3 grid(12, rows / 128, 2);
        gemm_xz<<<grid, 256>>>(Ah[l], Al[l], ldas[l],
                               whi + woff[l][0], wlo + woff[l][0],
                               whi + woff[l][1], wlo + woff[l][1],
                               bi_[l][0], bi_[l][1],
                               xzf, xzb, K, T, mk + moff[l]);

        gru_rec_kernel<<<128, REC_THREADS, REC_SMEM>>>(
            xzf, xzb, r_[l][0], r_[l][1], bi_[l][0], bi_[l][1],
            mk + moff[l], Y32[l], Yh[l], Yl[l],
            (l < 3) ? (mk + moff[l + 1]) : nullptr,
            T, fbase[l], (l == 3) ? 1 : 0, hid);
    }
}

// round 15
// speedup vs baseline: 1.2988x; 1.0779x over previous
#include <cuda_runtime.h>
#include <cuda_bf16.h>
#include <cuda_fp16.h>
#include <cstdint>

// ============================================================================
// 4-layer pyramidal BiGRU. B=32, H=512, 3H=1536.
// Layers l=0..3: T = 1024,512,256,128 ; din = 240,2048,2048,2048
// All tensor math in fp16 (A/h single, W hi+lo 2-term split), fp32 carry.
// ============================================================================

#define REC_THREADS 256

// ---------------- static device scratch ----------------
__device__ float g_xzf[50331648];                 // [32][1024][1536] max
__device__ float g_xzb[50331648];
__device__ unsigned int g_flag[2 * 512];          // [dir][64 ctas] stride-8
__device__ unsigned char g_mask[65536];           // per-layer offsets
__device__ __half g_wh[19611648], g_wl[19611648]; // weights fp16 hi/lo
__device__ __half g_in[7864320];                  // input fp16 [32*1024][240]
__device__ __half g_y0[33554432];                 // [32][1024][1024] fp16
__device__ __half g_y1[16777216];                 // [32][512][1024] fp16
__device__ __half g_hh[4 * 16384];                // [parity][dir][32][512]

// ---------------- mma / ldmatrix ----------------
#define MMA_F16(c, a, b0, b1)                                               \
    asm volatile("mma.sync.aligned.m16n8k16.row.col.f32.f16.f16.f32 "       \
        "{%0,%1,%2,%3}, {%4,%5,%6,%7}, {%8,%9}, {%0,%1,%2,%3};"             \
        : "+f"((c)[0]), "+f"((c)[1]), "+f"((c)[2]), "+f"((c)[3])            \
        : "r"((a)[0]), "r"((a)[1]), "r"((a)[2]), "r"((a)[3]),               \
          "r"(b0), "r"(b1))

#define LDSM4(R, addr)                                                      \
    asm volatile("ldmatrix.sync.aligned.m8n8.x4.shared.b16 "                \
        "{%0,%1,%2,%3}, [%4];"                                              \
        : "=r"((R)[0]), "=r"((R)[1]), "=r"((R)[2]), "=r"((R)[3])            \
        : "r"(addr))

#define LDSM4T(R, addr)                                                     \
    asm volatile("ldmatrix.sync.aligned.m8n8.x4.trans.shared.b16 "          \
        "{%0,%1,%2,%3}, [%4];"                                              \
        : "=r"((R)[0]), "=r"((R)[1]), "=r"((R)[2]), "=r"((R)[3])            \
        : "r"(addr))

__device__ __forceinline__ unsigned int smaddr(const void* p) {
    return (unsigned int)__cvta_generic_to_shared(p);
}
__device__ __forceinline__ unsigned int h2pack(float a, float b) {
    __half2 h = __floats2half2_rn(a, b);
    return *reinterpret_cast<unsigned int*>(&h);
}

// ============================================================================
// prep kernel: weights -> fp16 hi/lo; input -> fp16 single; layer-0 mask;
// flag reset.
// ============================================================================
__device__ __forceinline__ void cvt4h(float4 v, uint2& hi, uint2& lo) {
    __half2 h0 = __floats2half2_rn(v.x, v.y);
    __half2 h1 = __floats2half2_rn(v.z, v.w);
    float2 f0 = __half22float2(h0);
    float2 f1 = __half22float2(h1);
    __half2 l0 = __floats2half2_rn(v.x - f0.x, v.y - f0.y);
    __half2 l1 = __floats2half2_rn(v.z - f1.x, v.w - f1.y);
    hi.x = *(unsigned int*)&h0; hi.y = *(unsigned int*)&h1;
    lo.x = *(unsigned int*)&l0; lo.y = *(unsigned int*)&l1;
}

#define WSZ0 368640
#define WSZ1 3145728

__global__ void prep_kernel(const float* __restrict__ in,
                            const float* w0, const float* w1, const float* w2,
                            const float* w3, const float* w4, const float* w5,
                            const float* w6, const float* w7) {
    const float* ws[8] = {w0, w1, w2, w3, w4, w5, w6, w7};
    const int sz[8]  = {WSZ0, WSZ0, WSZ1, WSZ1, WSZ1, WSZ1, WSZ1, WSZ1};
    const int off[8] = {0, WSZ0, 2 * WSZ0, 2 * WSZ0 + WSZ1, 2 * WSZ0 + 2 * WSZ1,
                        2 * WSZ0 + 3 * WSZ1, 2 * WSZ0 + 4 * WSZ1, 2 * WSZ0 + 5 * WSZ1};
    const int gid = blockIdx.x * blockDim.x + threadIdx.x;
    const int stride = gridDim.x * blockDim.x;

    #pragma unroll 1
    for (int w = 0; w < 8; ++w) {
        const float4* W = (const float4*)ws[w];
        uint2* hi = (uint2*)(g_wh + off[w]);
        uint2* lo = (uint2*)(g_wl + off[w]);
        int n4 = sz[w] >> 2;
        for (int i = gid; i < n4; i += stride) {
            uint2 h, l; cvt4h(__ldg(W + i), h, l);
            hi[i] = h; lo[i] = l;
        }
    }
    {
        const float4* X = (const float4*)in;
        uint2* dst = (uint2*)g_in;
        for (int i = gid; i < (7864320 >> 2); i += stride) {
            float4 v = __ldg(X + i);
            __half2 h0 = __floats2half2_rn(v.x, v.y);
            __half2 h1 = __floats2half2_rn(v.z, v.w);
            uint2 o = {*(unsigned int*)&h0, *(unsigned int*)&h1};
            dst[i] = o;
        }
    }
    for (int r = gid; r < 32768; r += stride) {
        const float4* p = (const float4*)(in + (size_t)r * 240);
        bool any = false;
        for (int i = 0; i < 60; ++i) {
            float4 v = __ldg(p + i);
            any = any | (v.x != 0.f) | (v.y != 0.f) | (v.z != 0.f) | (v.w != 0.f);
            if (any) break;
        }
        g_mask[r] = any ? 1 : 0;
    }
    for (int i = gid; i < 2 * 512; i += stride) g_flag[i] = 0u;
}

// ============================================================================
// Input-projection GEMM: fp16 A (single) x fp16 W (hi+lo), 2-term split.
// Tile 128x128x16, 2 CTAs/SM, masked-tile skip, register prefetch,
// single SMEM buffer (round-10/11 proven pipeline).
// ============================================================================
__global__ void __launch_bounds__(256, 2) gemm_xz(
    const __half* __restrict__ A, int lda,
    const __half* __restrict__ WhF, const __half* __restrict__ WlF,
    const __half* __restrict__ WhB, const __half* __restrict__ WlB,
    const float* __restrict__ biasF, const float* __restrict__ biasB,
    float* __restrict__ Cf, float* __restrict__ Cb,
    int K, int Tcur, const unsigned char* __restrict__ mask) {
    __shared__ __align__(16) __half a_s[128 * 24];
    __shared__ __align__(16) __half w_hi[16 * 136], w_lo[16 * 136];

    const int dir = blockIdx.z;
    const int rev = dir;
    const __half* Wh = dir ? WhB : WhF;
    const __half* Wl = dir ? WlB : WlF;
    const float* bias = dir ? biasB : biasF;
    float* C = dir ? Cb : Cf;

    const int tid  = threadIdx.x;
    const int lane = tid & 31, wid = tid >> 5;
    const int g = lane >> 2, t4 = lane & 3;
    const int warpM = wid & 3, warpN = wid >> 2;
    const int m0 = blockIdx.y << 7, n0 = blockIdx.x << 7;

    {
        const int b  = m0 / Tcur;
        const int t0 = m0 - b * Tcur;
        const int ttmin = rev ? (Tcur - 128 - t0) : t0;
        if (mask[b * Tcur + ttmin] == 0) return;
    }

    const int ar = tid >> 1;           // A row 0..127
    const int ak = (tid & 1) << 3;     // k offset 0/8
    const int wk = tid >> 4;           // W k row 0..15
    const int wc = (tid & 15) << 3;    // W col 0..120

    const __half* pA;
    {
        int m  = m0 + ar;
        int bi = m / Tcur;
        int t  = m - bi * Tcur;
        int tt = rev ? (Tcur - 1 - t) : t;
        pA = A + ((size_t)bi * Tcur + tt) * lda + ak;
    }
    const __half* pWh = Wh + (size_t)wk * 1536 + n0 + wc;
    const __half* pWl = Wl + (size_t)wk * 1536 + n0 + wc;

    const int aRowL = warpM * 32 + (lane & 15);
    const int aKofL = (lane & 16) >> 1;
    const unsigned int aAddr = smaddr(a_s) + (unsigned)((aRowL * 24 + aKofL) * 2);
    const int bCol = warpN * 64 + ((lane & 16) >> 1);
    const unsigned int bHiAddr = smaddr(w_hi) + (unsigned)(((lane & 15) * 136 + bCol) * 2);
    const unsigned int bLoAddr = smaddr(w_lo) + (unsigned)(((lane & 15) * 136 + bCol) * 2);

    float c_[2][8][4];
    #pragma unroll
    for (int mt = 0; mt < 2; ++mt)
        #pragma unroll
        for (int nt = 0; nt < 8; ++nt)
            #pragma unroll
            for (int i = 0; i < 4; ++i) c_[mt][nt][i] = 0.f;

    const int NT = K >> 4;
    uint4 rA  = *(const uint4*)pA;
    uint4 rWh = *(const uint4*)pWh;
    uint4 rWl = *(const uint4*)pWl;

    for (int kt = 0; kt < NT; ++kt) {
        *(uint4*)(a_s + ar * 24 + ak)   = rA;
        *(uint4*)(w_hi + wk * 136 + wc) = rWh;
        *(uint4*)(w_lo + wk * 136 + wc) = rWl;
        __syncthreads();

        if (kt + 1 < NT) {
            int k0 = (kt + 1) << 4;
            rA  = *(const uint4*)(pA + k0);
            rWh = *(const uint4*)(pWh + (size_t)k0 * 1536);
            rWl = *(const uint4*)(pWl + (size_t)k0 * 1536);
        }

        unsigned int af[2][4];
        #pragma unroll
        for (int mt = 0; mt < 2; ++mt)
            LDSM4(af[mt], aAddr + mt * 768);

        #pragma unroll
        for (int p = 0; p < 4; ++p) {
            unsigned int bh[4], bl[4];
            LDSM4T(bh, bHiAddr + p * 32);
            LDSM4T(bl, bLoAddr + p * 32);
            #pragma unroll
            for (int s = 0; s < 2; ++s) {
                const int nt = 2 * p + s;
                #pragma unroll
                for (int mt = 0; mt < 2; ++mt) {
                    MMA_F16(c_[mt][nt], af[mt], bh[2 * s], bh[2 * s + 1]);
                    MMA_F16(c_[mt][nt], af[mt], bl[2 * s], bl[2 * s + 1]);
                }
            }
        }
        __syncthreads();
    }

    #pragma unroll
    for (int nt = 0; nt < 8; ++nt) {
        int col = n0 + warpN * 64 + nt * 8 + t4 * 2;
        float bx = __ldg(bias + col);
        float by = __ldg(bias + col + 1);
        #pragma unroll
        for (int mt = 0; mt < 2; ++mt) {
            int r = m0 + warpM * 32 + mt * 16 + g;
            float2 o0 = {c_[mt][nt][0] + bx, c_[mt][nt][1] + by};
            float2 o1 = {c_[mt][nt][2] + bx, c_[mt][nt][3] + by};
            *(float2*)(C + (size_t)r * 1536 + col)       = o0;
            *(float2*)(C + (size_t)(r + 8) * 1536 + col) = o1;
        }
    }
}

// ============================================================================
// Recurrence — round-14 structure (per-warp dataflow, fp16 h single, W fp16
// hi/lo 2-term); y output now a SINGLE fp16 store.
// SMEM: ah[32][520] fp16 | part[8][3][256] f32 | hp[256] f32
// ============================================================================
#define LDK 520
#define REC_SMEM (32 * LDK * 2 + 8 * 3 * 256 * 4 + 256 * 4)

__global__ void __launch_bounds__(REC_THREADS, 1) gru_rec_kernel(
    const float* __restrict__ xzf, const float* __restrict__ xzb,
    const float* __restrict__ rkf, const float* __restrict__ rkb,
    const float* __restrict__ bf,  const float* __restrict__ bb,
    const unsigned char* __restrict__ mask,
    float* __restrict__ y32,
    __half* __restrict__ yh,
    unsigned char* __restrict__ nextmask,
    int T, int flagBase, int writeHidden, float* __restrict__ hiddenOut) {
    extern __shared__ __align__(16) char smraw[];
    __half* sh_ah = (__half*)smraw;                       // [32][520]
    float* sh_part = (float*)(sh_ah + 32 * LDK);          // [8][3][256]
    float* sh_hp   = sh_part + 8 * 3 * 256;               // [256]

    const int tid  = threadIdx.x;
    const int lane = tid & 31, wid = tid >> 5;
    const int dir = blockIdx.x >> 6;
    const int j   = blockIdx.x & 63;
    const int cb  = j << 3;
    const int b   = tid >> 3;
    const int c8  = tid & 7;
    const int col = cb + c8;

    const float* xz = dir ? xzb : xzf;
    const float* rk = dir ? rkb : rkf;
    const float* bi = (dir ? bb : bf) + 1536;   // b[1]

    sh_hp[tid] = 0.f;

    // ---- B-fragment preload (fp16 hi/lo): warp w owns kt = 4w..4w+3 ----
    const int t4 = lane & 3;
    const int gcol = lane >> 2;
    unsigned int Bh0[3][4], Bh1[3][4], Bl0[3][4], Bl1[3][4];
    #pragma unroll 1
    for (int gate = 0; gate < 3; ++gate) {
        const float* wcolp = rk + gate * 512 + cb + gcol;
        #pragma unroll
        for (int q = 0; q < 4; ++q) {
            int k0 = (wid * 4 + q) * 16 + t4 * 2;
            float w00 = __ldg(wcolp + (size_t)(k0)     * 1536);
            float w01 = __ldg(wcolp + (size_t)(k0 + 1) * 1536);
            float w10 = __ldg(wcolp + (size_t)(k0 + 8) * 1536);
            float w11 = __ldg(wcolp + (size_t)(k0 + 9) * 1536);
            __half h00 = __float2half_rn(w00), h01 = __float2half_rn(w01);
            __half h10 = __float2half_rn(w10), h11 = __float2half_rn(w11);
            Bh0[gate][q] = ((unsigned)*(unsigned short*)&h01 << 16) | *(unsigned short*)&h00;
            Bh1[gate][q] = ((unsigned)*(unsigned short*)&h11 << 16) | *(unsigned short*)&h10;
            Bl0[gate][q] = h2pack(w00 - __half2float(h00), w01 - __half2float(h01));
            Bl1[gate][q] = h2pack(w10 - __half2float(h10), w11 - __half2float(h11));
        }
    }
    const float bz = __ldg(bi + col);
    const float br = __ldg(bi + 512 + col);
    const float bh = __ldg(bi + 1024 + col);
    __syncthreads();

    const unsigned int aB0 = smaddr(sh_ah) +
        (unsigned)((((lane & 15)) * LDK + ((lane >> 4) << 3)) * 2) + (unsigned)(wid * 128);
    const unsigned int aB1 = aB0 + (unsigned)(16 * LDK * 2);

    unsigned int* myflag = g_flag + dir * 512 + j * 8;
    const unsigned int* pollflag = g_flag + dir * 512 + (wid * 8 + (lane & 7)) * 8;
    const bool maskWriter = (nextmask != nullptr) && (dir == 0) && (j == 0) && (c8 == 0);
    unsigned char mprev = 0;

    for (int t = 0; t < T; ++t) {
        const int tsrc = dir ? (T - 1 - t) : t;
        const size_t xoff = ((size_t)b * T + t) * 1536;
        const float x0 = __ldg(xz + xoff + col);
        const float x1 = __ldg(xz + xoff + 512 + col);
        const float x2 = __ldg(xz + xoff + 1024 + col);
        const unsigned char m = mask[b * T + tsrc];

        if (t > 0) {
            // ---- per-warp: wait for THIS warp's 8 producer CTAs ----
            {
                const unsigned int target = (unsigned int)(flagBase + t);
                unsigned int v;
                do {
                    asm volatile("ld.acquire.gpu.global.u32 %0, [%1];"
                                 : "=r"(v) : "l"(pollflag) : "memory");
                } while (__any_sync(0xffffffffu, v < target));
            }

            // ---- per-warp: stage own 64-col fp16 chunk (4KB) ----
            const size_t hsrc = (size_t)(((t & 1) * 2 + dir)) << 14;
            const __half* gh = g_hh + hsrc + wid * 64;
            uint4 hv[8];
            #pragma unroll
            for (int q = 0; q < 8; ++q) {
                int v = q * 32 + lane;
                int bb2 = v >> 3, kc = v & 7;
                hv[q] = __ldcg((const uint4*)(gh + (bb2 << 9) + kc * 8));
            }
            #pragma unroll
            for (int q = 0; q < 8; ++q) {
                int v = q * 32 + lane;
                int bb2 = v >> 3, kc = v & 7;
                *(uint4*)(sh_ah + bb2 * LDK + wid * 64 + kc * 8) = hv[q];
            }
            __syncwarp();

            // ---- per-warp mma: 4 kt x (2 LDSM + 12 mma) ----
            float acc[3][2][4];
            #pragma unroll
            for (int gg = 0; gg < 3; ++gg)
                #pragma unroll
                for (int mt = 0; mt < 2; ++mt)
                    #pragma unroll
                    for (int i = 0; i < 4; ++i) acc[gg][mt][i] = 0.f;

            #pragma unroll
            for (int q = 0; q < 4; ++q) {
                unsigned int ah[2][4];
                LDSM4(ah[0], aB0 + q * 32);
                LDSM4(ah[1], aB1 + q * 32);
                #pragma unroll
                for (int gg = 0; gg < 3; ++gg) {
                    #pragma unroll
                    for (int mt = 0; mt < 2; ++mt) {
                        MMA_F16(acc[gg][mt], ah[mt], Bh0[gg][q], Bh1[gg][q]);
                        MMA_F16(acc[gg][mt], ah[mt], Bl0[gg][q], Bl1[gg][q]);
                    }
                }
            }
            const int row = lane >> 2, cq = (lane & 3) << 1;
            #pragma unroll
            for (int gg = 0; gg < 3; ++gg) {
                #pragma unroll
                for (int mt = 0; mt < 2; ++mt) {
                    float* gp = sh_part + (wid * 3 + gg) * 256 + (mt * 16 + row) * 8 + cq;
                    gp[0]  = acc[gg][mt][0];
                    gp[1]  = acc[gg][mt][1];
                    gp[64] = acc[gg][mt][2];
                    gp[65] = acc[gg][mt][3];
                }
            }
            __syncthreads();   // join
        }

        // ---- scalar epilogue ----
        float iz = bz, ir = br, ic = bh;
        if (t > 0) {
            #pragma unroll
            for (int w = 0; w < 8; ++w) {
                iz += sh_part[(w * 3 + 0) * 256 + tid];
                ir += sh_part[(w * 3 + 1) * 256 + tid];
                ic += sh_part[(w * 3 + 2) * 256 + tid];
            }
        }

        const float zg = 1.f / (1.f + expf(-(x0 + iz)));
        const float rg = 1.f / (1.f + expf(-(x1 + ir)));
        const float hh = tanhf(x2 + rg * ic);
        const float hp = sh_hp[tid];
        const float hn = zg * hp + (1.f - zg) * hh;
        const float hsel = m ? hn : hp;
        const float yval = m ? hn : 0.f;
        sh_hp[tid] = hsel;

        // ---- critical path: publish h (single fp16) + flag ----
        const size_t hdst = (size_t)((((t + 1) & 1) * 2 + dir)) << 14;
        g_hh[hdst + (b << 9) + col] = __float2half_rn(hsel);
        __syncthreads();
        if (tid == 0) {
            unsigned int v = (unsigned int)(flagBase + t + 1);
            asm volatile("st.release.gpu.global.u32 [%0], %1;"
                         :: "l"(myflag), "r"(v) : "memory");
        }

        // ---- off critical path: outputs ----
        const size_t yidx = ((size_t)b * T + tsrc) * 1024 + (dir << 9) + col;
        if (yh) yh[yidx] = __float2half_rn(yval);
        if (y32) y32[yidx] = yval;
        if (writeHidden && t == T - 1)
            hiddenOut[(b << 10) + (dir << 9) + col] = hsel;
        if (maskWriter) {
            if ((t & 1) == 0) mprev = m;
            else nextmask[b * (T >> 1) + (t >> 1)] = (unsigned char)(mprev | m);
        }
    }
}

// ============================================================================
// Launch sequence (graph-capturable)
// ============================================================================
extern "C" void kernel_launch(void* const* d_in, const int* in_sizes, int n_in,
                              void* d_out, int out_size) {
    (void)in_sizes; (void)n_in; (void)out_size;
    const float* inputs = (const float*)d_in[0];

    const float *k_[4][2], *r_[4][2], *bi_[4][2];
    for (int l = 0; l < 4; ++l)
        for (int d = 0; d < 2; ++d) {
            int base = 3 + l * 6 + d * 3;
            k_[l][d]  = (const float*)d_in[base + 0];
            r_[l][d]  = (const float*)d_in[base + 1];
            bi_[l][d] = (const float*)d_in[base + 2];
        }

    float *xzf, *xzb;
    unsigned char* mk;
    __half *wh, *wl, *inh, *y0, *y1;
    cudaGetSymbolAddress((void**)&xzf, g_xzf);
    cudaGetSymbolAddress((void**)&xzb, g_xzb);
    cudaGetSymbolAddress((void**)&mk, g_mask);
    cudaGetSymbolAddress((void**)&wh, g_wh);
    cudaGetSymbolAddress((void**)&wl, g_wl);
    cudaGetSymbolAddress((void**)&inh, g_in);
    cudaGetSymbolAddress((void**)&y0, g_y0);
    cudaGetSymbolAddress((void**)&y1, g_y1);

    cudaFuncSetAttribute(gru_rec_kernel,
                         cudaFuncAttributeMaxDynamicSharedMemorySize, REC_SMEM);

    float* outp = (float*)d_out;
    float* hid  = outp + (size_t)32 * 128 * 1024;

    prep_kernel<<<2048, 256>>>(inputs, k_[0][0], k_[0][1], k_[1][0], k_[1][1],
                               k_[2][0], k_[2][1], k_[3][0], k_[3][1]);

    const int Ts[4]   = {1024, 512, 256, 128};
    const int Ks[4]   = {240, 2048, 2048, 2048};
    const int ldas[4] = {240, 2048, 2048, 2048};
    const int woff[4][2] = {{0, WSZ0},
                            {2 * WSZ0, 2 * WSZ0 + WSZ1},
                            {2 * WSZ0 + 2 * WSZ1, 2 * WSZ0 + 3 * WSZ1},
                            {2 * WSZ0 + 4 * WSZ1, 2 * WSZ0 + 5 * WSZ1}};
    const int moff[4]  = {0, 32768, 49152, 57344};
    const int fbase[4] = {0, 1024, 1536, 1792};

    const __half* Ah[4] = {inh, y0, y1, y0};
    __half* Yh[4] = {y0, y1, y0, nullptr};
    float* Y32[4] = {nullptr, nullptr, nullptr, outp};

    for (int l = 0; l < 4; ++l) {
        const int T = Ts[l], K = Ks[l];
        const int rows = 32 * T;

        dim3 grid(12, rows / 128, 2);
        gemm_xz<<<grid, 256>>>(Ah[l], ldas[l],
                               wh + woff[l][0], wl + woff[l][0],
                               wh + woff[l][1], wl + woff[l][1],
                               bi_[l][0], bi_[l][1],
                               xzf, xzb, K, T, mk + moff[l]);

        gru_rec_kernel<<<128, REC_THREADS, REC_SMEM>>>(
            xzf, xzb, r_[l][0], r_[l][1], bi_[l][0], bi_[l][1],
            mk + moff[l], Y32[l], Yh[l],
            (l < 3) ? (mk + moff[l + 1]) : nullptr,
            T, fbase[l], (l == 3) ? 1 : 0, hid);
    }
}